// round 8
// baseline (speedup 1.0000x reference)
#include <cuda_runtime.h>
#include <cstdint>

#define BB 512
#define SS 64
#define DD 256
#define NN 100000
#define NM1 99999
#define D2 512
#define NBLK 782            // ceil(99999/128)

// ---- scratch (device globals: no allocation allowed) ----
__device__ float g_avlast[BB * D2];
__device__ float g_h[BB * D2];
__device__ float g_lasth[BB * DD];
__device__ float g_lse[BB];
__device__ float g_pmax[BB * NBLK];
__device__ float g_psum[BB * NBLK];
__device__ float g_logits_fb[BB * NM1];

// ============================================================================
// K0: session length -> last id -> gather + dual adjacency row-aggregation
// ============================================================================
__global__ void k_avlast(const float* __restrict__ emb,
                         const float* __restrict__ adj_in,
                         const float* __restrict__ adj_out,
                         const float* __restrict__ mask,
                         const int* __restrict__ item,
                         const int* __restrict__ alias_) {
    int b = blockIdx.x, t = threadIdx.x;   // 256 threads
    __shared__ float ain[SS], aout[SS];
    __shared__ int items[SS];
    __shared__ int s_last;
    if (t == 0) {
        float s = 0.f;
        for (int i = 0; i < SS; i++) s += mask[b * SS + i];
        int rm = (int)s;
        s_last = alias_[b * SS + rm - 1];
    }
    __syncthreads();
    int last = s_last;
    if (t < SS) {
        ain[t]   = adj_in [((size_t)b * SS + last) * SS + t];
        aout[t]  = adj_out[((size_t)b * SS + last) * SS + t];
        items[t] = item[b * SS + t];
    }
    __syncthreads();
    int d = t;
    float aI = 0.f, aO = 0.f;
#pragma unroll 8
    for (int k = 0; k < SS; k++) {
        float e = emb[(size_t)items[k] * DD + d];
        aI = fmaf(ain[k],  e, aI);
        aO = fmaf(aout[k], e, aO);
    }
    g_avlast[b * D2 + d]      = aI;
    g_avlast[b * D2 + DD + d] = aO;
}

__device__ __forceinline__ uint32_t f2tf(float x) {
    uint32_t r;
    asm("cvt.rna.tf32.f32 %0, %1;" : "=r"(r) : "f"(x));
    return r;
}

// ============================================================================
// K1/K2: fp32 GEMM, 64(M)x32(N) tile, 128 threads, 4x4 micro-tile, k-major
//        smem (2x LDS.128 per kk for 16 FMA), register-prefetch double buffer.
//        mode: 1 = relu epilogue, 2 = round output to tf32 (for MMA consumer)
// ============================================================================
__global__ __launch_bounds__(128) void k_gemm(const float* __restrict__ A,
                                              const float* __restrict__ Bm,
                                              float* __restrict__ C,
                                              int M, int K, int N, int mode) {
    __shared__ float As[16][68];   // [k][m], pitch 68 (16B aligned rows)
    __shared__ float Bs[16][36];   // [k][n]
    int t = threadIdx.x;
    int tx = t & 7, ty = t >> 3;               // 8 x 16 thread grid
    int row0 = blockIdx.y * 64, col0 = blockIdx.x * 32;

    int ra = t >> 2, ka = (t & 3) << 2;        // A staging coords
    int kb = t >> 3, cb = (t & 7) << 2;        // B staging coords
    const float* pA0 = A + (size_t)(row0 + ra) * K + ka;
    const float* pA1 = A + (size_t)(row0 + ra + 32) * K + ka;
    const float* pB  = Bm + (size_t)kb * N + col0 + cb;

    float4 fa0 = *(const float4*)pA0;
    float4 fa1 = *(const float4*)pA1;
    float4 fb  = *(const float4*)pB;

    float acc[4][4] = {};
    for (int k0 = 0; k0 < K; k0 += 16) {
        As[ka][ra]           = fa0.x; As[ka + 1][ra]      = fa0.y;
        As[ka + 2][ra]       = fa0.z; As[ka + 3][ra]      = fa0.w;
        As[ka][ra + 32]      = fa1.x; As[ka + 1][ra + 32] = fa1.y;
        As[ka + 2][ra + 32]  = fa1.z; As[ka + 3][ra + 32] = fa1.w;
        *(float4*)&Bs[kb][cb] = fb;
        __syncthreads();
        if (k0 + 16 < K) {                     // prefetch next chunk (overlaps compute)
            fa0 = *(const float4*)(pA0 + k0 + 16);
            fa1 = *(const float4*)(pA1 + k0 + 16);
            fb  = *(const float4*)(pB + (size_t)(k0 + 16) * N);
        }
#pragma unroll
        for (int kk = 0; kk < 16; kk++) {
            float4 a = *(float4*)&As[kk][ty * 4];
            float4 b = *(float4*)&Bs[kk][tx * 4];
            float av[4] = {a.x, a.y, a.z, a.w};
            float bv[4] = {b.x, b.y, b.z, b.w};
#pragma unroll
            for (int i = 0; i < 4; i++)
#pragma unroll
                for (int j = 0; j < 4; j++)
                    acc[i][j] = fmaf(av[i], bv[j], acc[i][j]);
        }
        __syncthreads();
    }
#pragma unroll
    for (int i = 0; i < 4; i++) {
        float4 v;
        float* vp = &v.x;
#pragma unroll
        for (int j = 0; j < 4; j++) {
            float x = acc[i][j];
            if (mode == 1) x = fmaxf(x, 0.f);
            if (mode == 2) x = __uint_as_float(f2tf(x));
            vp[j] = x;
        }
        *(float4*)&C[(size_t)(row0 + ty * 4 + i) * N + col0 + tx * 4] = v;
    }
}

// ============================================================================
// K3: logits[512,99999] = last_h[512,256] @ emb[1:].T  (TF32 mma.sync)
//     128x128 tile, 8 warps (4M x 2N), K-chunk 32, cp.async 2-stage pipeline,
//     ldmatrix.x4 fragments, fused per-row (max, sumexp) partials.
//     launch_bounds(256,3): cap regs so 3 CTAs/SM co-reside (24 warps).
// ============================================================================
__device__ __forceinline__ void mma_tf32(float* c, uint32_t a0, uint32_t a1,
                                         uint32_t a2, uint32_t a3,
                                         uint32_t b0, uint32_t b1) {
    asm volatile("mma.sync.aligned.m16n8k8.row.col.f32.tf32.tf32.f32 "
                 "{%0,%1,%2,%3},{%4,%5,%6,%7},{%8,%9},{%0,%1,%2,%3};"
                 : "+f"(c[0]), "+f"(c[1]), "+f"(c[2]), "+f"(c[3])
                 : "r"(a0), "r"(a1), "r"(a2), "r"(a3), "r"(b0), "r"(b1));
}

#define PITCH 36                       // words per smem row (144B, conflict-free LDSM)
#define STG_W (128 * PITCH)            // words per stage matrix
#define SMEM_LOGITS_BYTES (4 * STG_W * 4)

__device__ __forceinline__ void stage_logits(uint32_t sA, uint32_t sB,
                                             const float* __restrict__ Ah,
                                             const float* __restrict__ emb,
                                             int mt, int nt, int k0, int t) {
#pragma unroll
    for (int u0 = 0; u0 < 4; u0++) {
        int u = t + u0 * 256;
        int r = u >> 3, c = (u & 7) << 2;       // c in floats (16B chunks)
        uint32_t da = sA + (uint32_t)(r * PITCH + c) * 4;
        const float* srcA = Ah + (size_t)(mt + r) * DD + k0 + c;
        asm volatile("cp.async.cg.shared.global [%0], [%1], 16;\n"
                     :: "r"(da), "l"(srcA));
        int er = nt + 1 + r;
        uint32_t db = sB + (uint32_t)(r * PITCH + c) * 4;
        const float* srcB = emb + (size_t)(er < NN ? er : 0) * DD + k0 + c;
        int sz = (er < NN) ? 16 : 0;
        asm volatile("cp.async.cg.shared.global [%0], [%1], 16, %2;\n"
                     :: "r"(db), "l"(srcB), "r"(sz));
    }
}

__global__ __launch_bounds__(256, 3) void k_logits(const float* __restrict__ Ah,
                                                   const float* __restrict__ emb,
                                                   float* __restrict__ out) {
    extern __shared__ float smem[];
    uint32_t sbase = (uint32_t)__cvta_generic_to_shared(smem);
    const uint32_t ASZ = STG_W * 4;   // bytes per stage matrix
    uint32_t sA[2] = { sbase,           sbase + ASZ };
    uint32_t sB[2] = { sbase + 2 * ASZ, sbase + 3 * ASZ };

    int mt = blockIdx.x * 128;
    int nt = blockIdx.y * 128;
    int t = threadIdx.x;
    int warp = t >> 5, lane = t & 31;
    int wm = warp >> 1, wn = warp & 1;
    int g = lane >> 2, tq = lane & 3;
    // ldmatrix lane addressing
    int lr = lane & 7, bq = lane >> 3;
    int rowadd = lr + ((bq & 1) << 3);
    int coladd = (bq >> 1) << 2;

    // loop-invariant LDSM word offsets (ks added as immediate in unrolled loop)
    uint32_t offA[2], offB[4];
#pragma unroll
    for (int mi = 0; mi < 2; mi++)
        offA[mi] = (uint32_t)((wm * 32 + mi * 16 + rowadd) * PITCH + coladd) * 4;
#pragma unroll
    for (int np = 0; np < 4; np++)
        offB[np] = (uint32_t)((wn * 64 + np * 16 + rowadd) * PITCH + coladd) * 4;

    float c[2][8][4];
#pragma unroll
    for (int mi = 0; mi < 2; mi++)
#pragma unroll
        for (int ni = 0; ni < 8; ni++)
#pragma unroll
            for (int q = 0; q < 4; q++) c[mi][ni][q] = 0.f;

    stage_logits(sA[0], sB[0], Ah, emb, mt, nt, 0, t);
    asm volatile("cp.async.commit_group;");

    for (int s = 0; s < 8; s++) {
        if (s < 7) stage_logits(sA[(s + 1) & 1], sB[(s + 1) & 1], Ah, emb, mt, nt, (s + 1) * 32, t);
        asm volatile("cp.async.commit_group;");
        asm volatile("cp.async.wait_group 1;");
        __syncthreads();
        uint32_t cA = sA[s & 1], cB = sB[s & 1];
#pragma unroll
        for (int ks = 0; ks < 32; ks += 8) {
            uint32_t a[2][4];
#pragma unroll
            for (int mi = 0; mi < 2; mi++) {
                asm volatile("ldmatrix.sync.aligned.m8n8.x4.shared.b16 {%0,%1,%2,%3}, [%4];"
                             : "=r"(a[mi][0]), "=r"(a[mi][1]), "=r"(a[mi][2]), "=r"(a[mi][3])
                             : "r"(cA + offA[mi] + (uint32_t)(ks * 4)));
            }
#pragma unroll
            for (int np = 0; np < 4; np++) {
                uint32_t b0, b1, b2, b3;
                asm volatile("ldmatrix.sync.aligned.m8n8.x4.shared.b16 {%0,%1,%2,%3}, [%4];"
                             : "=r"(b0), "=r"(b1), "=r"(b2), "=r"(b3)
                             : "r"(cB + offB[np] + (uint32_t)(ks * 4)));
#pragma unroll
                for (int mi = 0; mi < 2; mi++) {
                    mma_tf32(c[mi][2 * np],     a[mi][0], a[mi][1], a[mi][2], a[mi][3], b0, b2);
                    mma_tf32(c[mi][2 * np + 1], a[mi][0], a[mi][1], a[mi][2], a[mi][3], b1, b3);
                }
            }
        }
        __syncthreads();
    }

    // ---- logits stores (c0/c1 -> row r0; c2/c3 -> row r0+8) ----
#pragma unroll
    for (int mi = 0; mi < 2; mi++) {
        int r0 = mt + wm * 32 + mi * 16 + g;
#pragma unroll
        for (int ni = 0; ni < 8; ni++) {
            int c0 = nt + wn * 64 + ni * 8 + 2 * tq;
            if (c0 < NM1) {
                out[(size_t)r0 * NM1 + c0]       = c[mi][ni][0];
                out[(size_t)(r0 + 8) * NM1 + c0] = c[mi][ni][2];
            }
            if (c0 + 1 < NM1) {
                out[(size_t)r0 * NM1 + c0 + 1]       = c[mi][ni][1];
                out[(size_t)(r0 + 8) * NM1 + c0 + 1] = c[mi][ni][3];
            }
        }
    }

    // ---- fused LSE partials: per-row (max, sumexp over this block's 128 cols) ----
    float* redM = smem;
    float* redS = smem + 256;
#pragma unroll
    for (int slot = 0; slot < 4; slot++) {
        int mi = slot >> 1, h = slot & 1;
        float m = -3.0e38f;
#pragma unroll
        for (int ni = 0; ni < 8; ni++) {
            int cbase = nt + wn * 64 + ni * 8 + 2 * tq;
            float v0 = (cbase     < NM1) ? c[mi][ni][2 * h]     : -3.0e38f;
            float v1 = (cbase + 1 < NM1) ? c[mi][ni][2 * h + 1] : -3.0e38f;
            m = fmaxf(m, fmaxf(v0, v1));
        }
        float sum = 0.f;
#pragma unroll
        for (int ni = 0; ni < 8; ni++) {
            int cbase = nt + wn * 64 + ni * 8 + 2 * tq;
            float v0 = (cbase     < NM1) ? c[mi][ni][2 * h]     : -3.0e38f;
            float v1 = (cbase + 1 < NM1) ? c[mi][ni][2 * h + 1] : -3.0e38f;
            sum += __expf(v0 - m) + __expf(v1 - m);
        }
#pragma unroll
        for (int off = 1; off <= 2; off <<= 1) {
            float m2 = __shfl_xor_sync(0xffffffffu, m, off);
            float s2 = __shfl_xor_sync(0xffffffffu, sum, off);
            float M = fmaxf(m, m2);
            sum = sum * __expf(m - M) + s2 * __expf(m2 - M);
            m = M;
        }
        if (tq == 0) {
            redM[(warp * 4 + slot) * 8 + g] = m;
            redS[(warp * 4 + slot) * 8 + g] = sum;
        }
    }
    __syncthreads();
    if (t < 128) {
        int wmr = t >> 5, slot = (t >> 3) & 3, gg = t & 7;
        int i1 = ((wmr * 2)     * 4 + slot) * 8 + gg;
        int i2 = ((wmr * 2 + 1) * 4 + slot) * 8 + gg;
        float m1 = redM[i1], s1 = redS[i1];
        float m2 = redM[i2], s2 = redS[i2];
        float M = fmaxf(m1, m2);
        float S = s1 * __expf(m1 - M) + s2 * __expf(m2 - M);
        int row = mt + wmr * 32 + (slot >> 1) * 16 + (slot & 1) * 8 + gg;
        g_pmax[(size_t)row * NBLK + blockIdx.y] = M;
        g_psum[(size_t)row * NBLK + blockIdx.y] = S;
    }
}

// ============================================================================
// K4: finalize LSE from per-block partials
// ============================================================================
__global__ void k_lsefin(float* __restrict__ lse) {
    int b = blockIdx.x, t = threadIdx.x;   // 256 threads
    float m = -3.0e38f, s = 0.f;
    for (int i = t; i < NBLK; i += 256) {
        float m2 = g_pmax[(size_t)b * NBLK + i];
        float s2 = g_psum[(size_t)b * NBLK + i];
        float M = fmaxf(m, m2);
        s = s * __expf(m - M) + s2 * __expf(m2 - M);
        m = M;
    }
    __shared__ float sm[256], ss[256];
    sm[t] = m; ss[t] = s;
    __syncthreads();
    for (int o = 128; o > 0; o >>= 1) {
        if (t < o) {
            float m2 = sm[t + o], s2 = ss[t + o];
            float M = fmaxf(sm[t], m2);
            ss[t] = ss[t] * __expf(sm[t] - M) + s2 * __expf(m2 - M);
            sm[t] = M;
        }
        __syncthreads();
    }
    if (t == 0) lse[b] = sm[0] + logf(ss[0]);
}

// ============================================================================
// K5: loss = -mean_b( logits[b, tar[b]-1] - lse[b] )
// ============================================================================
__global__ void k_loss(const float* __restrict__ logits, const float* __restrict__ lse,
                       const int* __restrict__ tar, float* __restrict__ loss_out) {
    __shared__ float red[512];
    int t = threadIdx.x;
    int tg = tar[t] - 1;
    red[t] = logits[(size_t)t * NM1 + tg] - lse[t];
    __syncthreads();
    for (int o = 256; o > 0; o >>= 1) {
        if (t < o) red[t] += red[t + o];
        __syncthreads();
    }
    if (t == 0) loss_out[0] = -red[0] / (float)BB;
}

// ============================================================================
// launch
// ============================================================================
extern "C" void kernel_launch(void* const* d_in, const int* in_sizes, int n_in,
                              void* d_out, int out_size) {
    const float* emb    = (const float*)d_in[0];
    const float* W1     = (const float*)d_in[1];
    const float* W2     = (const float*)d_in[2];
    const float* adjI   = (const float*)d_in[3];
    const float* adjO   = (const float*)d_in[4];
    const float* mask   = (const float*)d_in[5];
    const int*   item   = (const int*)d_in[6];
    const int*   alias_ = (const int*)d_in[7];
    const int*   tar    = (const int*)d_in[8];
    float* out = (float*)d_out;

    float *p_av, *p_h, *p_lh, *p_lse, *p_fb;
    cudaGetSymbolAddress((void**)&p_av,  g_avlast);
    cudaGetSymbolAddress((void**)&p_h,   g_h);
    cudaGetSymbolAddress((void**)&p_lh,  g_lasth);
    cudaGetSymbolAddress((void**)&p_lse, g_lse);
    cudaGetSymbolAddress((void**)&p_fb,  g_logits_fb);

    static int smem_set = 0;
    if (!smem_set) {
        cudaFuncSetAttribute(k_logits, cudaFuncAttributeMaxDynamicSharedMemorySize,
                             SMEM_LOGITS_BYTES);
        smem_set = 1;
    }

    const long long NL = (long long)BB * NM1;
    float *loss_ptr, *logits_ptr;
    if ((long long)out_size >= NL + 1)      { loss_ptr = out;  logits_ptr = out + 1; }
    else if ((long long)out_size == NL)     { loss_ptr = p_fb; logits_ptr = out; }
    else                                    { loss_ptr = out;  logits_ptr = p_fb; }

    k_avlast<<<BB, 256>>>(emb, adjI, adjO, mask, item, alias_);
    k_gemm<<<dim3(D2 / 32, BB / 64), 128>>>(p_av, W1, p_h,  BB, D2, D2, 1);  // relu(av@W1)
    k_gemm<<<dim3(DD / 32, BB / 64), 128>>>(p_h,  W2, p_lh, BB, D2, DD, 2);  // (h@W2) -> tf32
    k_logits<<<dim3(4, NBLK), 256, SMEM_LOGITS_BYTES>>>(p_lh, emb, logits_ptr);
    k_lsefin<<<BB, 256>>>(p_lse);
    k_loss<<<1, 512>>>(logits_ptr, p_lse, tar, loss_ptr);
}

// round 9
// speedup vs baseline: 1.5826x; 1.5826x over previous
#include <cuda_runtime.h>
#include <cstdint>

#define BB 512
#define SS 64
#define DD 256
#define NN 100000
#define NM1 99999
#define D2 512
#define NBLK 782            // ceil(99999/128)

// ---- scratch (device globals: no allocation allowed) ----
__device__ float g_avlast[BB * D2];
__device__ float g_h[BB * D2];
__device__ float g_lasth[BB * DD];
__device__ float g_lse[BB];
__device__ float g_pmax[BB * NBLK];
__device__ float g_psum[BB * NBLK];
__device__ float g_logits_fb[BB * NM1];

// ============================================================================
// K0: session length -> last id -> gather + dual adjacency row-aggregation
// ============================================================================
__global__ void k_avlast(const float* __restrict__ emb,
                         const float* __restrict__ adj_in,
                         const float* __restrict__ adj_out,
                         const float* __restrict__ mask,
                         const int* __restrict__ item,
                         const int* __restrict__ alias_) {
    int b = blockIdx.x, t = threadIdx.x;   // 256 threads
    __shared__ float ain[SS], aout[SS];
    __shared__ int items[SS];
    __shared__ int s_last;
    if (t == 0) {
        float s = 0.f;
        for (int i = 0; i < SS; i++) s += mask[b * SS + i];
        int rm = (int)s;
        s_last = alias_[b * SS + rm - 1];
    }
    __syncthreads();
    int last = s_last;
    if (t < SS) {
        ain[t]   = adj_in [((size_t)b * SS + last) * SS + t];
        aout[t]  = adj_out[((size_t)b * SS + last) * SS + t];
        items[t] = item[b * SS + t];
    }
    __syncthreads();
    int d = t;
    float aI = 0.f, aO = 0.f;
#pragma unroll 8
    for (int k = 0; k < SS; k++) {
        float e = emb[(size_t)items[k] * DD + d];
        aI = fmaf(ain[k],  e, aI);
        aO = fmaf(aout[k], e, aO);
    }
    g_avlast[b * D2 + d]      = aI;
    g_avlast[b * D2 + DD + d] = aO;
}

__device__ __forceinline__ uint32_t f2tf(float x) {
    uint32_t r;
    asm("cvt.rna.tf32.f32 %0, %1;" : "=r"(r) : "f"(x));
    return r;
}

// ============================================================================
// K1/K2: fp32 GEMM, 64(M)x32(N) tile, 128 threads, 4x4 micro-tile, k-major
//        smem (2x LDS.128 per kk for 16 FMA), register-prefetch double buffer.
//        mode: 1 = relu epilogue, 2 = round output to tf32 (for MMA consumer)
// ============================================================================
__global__ __launch_bounds__(128) void k_gemm(const float* __restrict__ A,
                                              const float* __restrict__ Bm,
                                              float* __restrict__ C,
                                              int M, int K, int N, int mode) {
    __shared__ float As[16][68];   // [k][m], pitch 68 (16B aligned rows)
    __shared__ float Bs[16][36];   // [k][n]
    int t = threadIdx.x;
    int tx = t & 7, ty = t >> 3;               // 8 x 16 thread grid
    int row0 = blockIdx.y * 64, col0 = blockIdx.x * 32;

    int ra = t >> 2, ka = (t & 3) << 2;        // A staging coords
    int kb = t >> 3, cb = (t & 7) << 2;        // B staging coords
    const float* pA0 = A + (size_t)(row0 + ra) * K + ka;
    const float* pA1 = A + (size_t)(row0 + ra + 32) * K + ka;
    const float* pB  = Bm + (size_t)kb * N + col0 + cb;

    float4 fa0 = *(const float4*)pA0;
    float4 fa1 = *(const float4*)pA1;
    float4 fb  = *(const float4*)pB;

    float acc[4][4] = {};
    for (int k0 = 0; k0 < K; k0 += 16) {
        As[ka][ra]           = fa0.x; As[ka + 1][ra]      = fa0.y;
        As[ka + 2][ra]       = fa0.z; As[ka + 3][ra]      = fa0.w;
        As[ka][ra + 32]      = fa1.x; As[ka + 1][ra + 32] = fa1.y;
        As[ka + 2][ra + 32]  = fa1.z; As[ka + 3][ra + 32] = fa1.w;
        *(float4*)&Bs[kb][cb] = fb;
        __syncthreads();
        if (k0 + 16 < K) {                     // prefetch next chunk (overlaps compute)
            fa0 = *(const float4*)(pA0 + k0 + 16);
            fa1 = *(const float4*)(pA1 + k0 + 16);
            fb  = *(const float4*)(pB + (size_t)(k0 + 16) * N);
        }
#pragma unroll
        for (int kk = 0; kk < 16; kk++) {
            float4 a = *(float4*)&As[kk][ty * 4];
            float4 b = *(float4*)&Bs[kk][tx * 4];
            float av[4] = {a.x, a.y, a.z, a.w};
            float bv[4] = {b.x, b.y, b.z, b.w};
#pragma unroll
            for (int i = 0; i < 4; i++)
#pragma unroll
                for (int j = 0; j < 4; j++)
                    acc[i][j] = fmaf(av[i], bv[j], acc[i][j]);
        }
        __syncthreads();
    }
#pragma unroll
    for (int i = 0; i < 4; i++) {
        float4 v;
        float* vp = &v.x;
#pragma unroll
        for (int j = 0; j < 4; j++) {
            float x = acc[i][j];
            if (mode == 1) x = fmaxf(x, 0.f);
            if (mode == 2) x = __uint_as_float(f2tf(x));
            vp[j] = x;
        }
        *(float4*)&C[(size_t)(row0 + ty * 4 + i) * N + col0 + tx * 4] = v;
    }
}

// ============================================================================
// K3: logits[512,99999] = last_h[512,256] @ emb[1:].T  (TF32 mma.sync)
//     128x128 tile, 8 warps (4M x 2N), K-chunk 32, cp.async 3-stage pipeline,
//     ldmatrix.x4 fragments, fused per-row (max, sumexp) partials.
//     No occupancy cap: 2 CTAs/SM with full register budget (no spills).
// ============================================================================
__device__ __forceinline__ void mma_tf32(float* c, uint32_t a0, uint32_t a1,
                                         uint32_t a2, uint32_t a3,
                                         uint32_t b0, uint32_t b1) {
    asm volatile("mma.sync.aligned.m16n8k8.row.col.f32.tf32.tf32.f32 "
                 "{%0,%1,%2,%3},{%4,%5,%6,%7},{%8,%9},{%0,%1,%2,%3};"
                 : "+f"(c[0]), "+f"(c[1]), "+f"(c[2]), "+f"(c[3])
                 : "r"(a0), "r"(a1), "r"(a2), "r"(a3), "r"(b0), "r"(b1));
}

#define PITCH 36                       // words per smem row (144B, conflict-free LDSM)
#define STG_W (128 * PITCH)            // words per stage matrix (18432 B)
#define NSTAGE 3
#define SMEM_LOGITS_BYTES (2 * NSTAGE * STG_W * 4)   // 110592 B

__device__ __forceinline__ void stage_logits(uint32_t sA, uint32_t sB,
                                             const float* __restrict__ Ah,
                                             const float* __restrict__ emb,
                                             int mt, int nt, int k0, int t) {
#pragma unroll
    for (int u0 = 0; u0 < 4; u0++) {
        int u = t + u0 * 256;
        int r = u >> 3, c = (u & 7) << 2;       // c in floats (16B chunks)
        uint32_t da = sA + (uint32_t)(r * PITCH + c) * 4;
        const float* srcA = Ah + (size_t)(mt + r) * DD + k0 + c;
        asm volatile("cp.async.cg.shared.global [%0], [%1], 16;\n"
                     :: "r"(da), "l"(srcA));
        int er = nt + 1 + r;
        uint32_t db = sB + (uint32_t)(r * PITCH + c) * 4;
        const float* srcB = emb + (size_t)(er < NN ? er : 0) * DD + k0 + c;
        int sz = (er < NN) ? 16 : 0;
        asm volatile("cp.async.cg.shared.global [%0], [%1], 16, %2;\n"
                     :: "r"(db), "l"(srcB), "r"(sz));
    }
}

__global__ __launch_bounds__(256) void k_logits(const float* __restrict__ Ah,
                                                const float* __restrict__ emb,
                                                float* __restrict__ out) {
    extern __shared__ float smem[];
    uint32_t sbase = (uint32_t)__cvta_generic_to_shared(smem);
    const uint32_t ASZ = STG_W * 4;   // bytes per stage matrix
    uint32_t sA[NSTAGE], sB[NSTAGE];
#pragma unroll
    for (int i = 0; i < NSTAGE; i++) {
        sA[i] = sbase + i * ASZ;
        sB[i] = sbase + (NSTAGE + i) * ASZ;
    }

    int mt = blockIdx.x * 128;
    int nt = blockIdx.y * 128;
    int t = threadIdx.x;
    int warp = t >> 5, lane = t & 31;
    int wm = warp >> 1, wn = warp & 1;
    int g = lane >> 2, tq = lane & 3;
    // ldmatrix lane addressing
    int lr = lane & 7, bq = lane >> 3;
    int rowadd = lr + ((bq & 1) << 3);
    int coladd = (bq >> 1) << 2;

    // loop-invariant LDSM word offsets (ks added as immediate in unrolled loop)
    uint32_t offA[2], offB[4];
#pragma unroll
    for (int mi = 0; mi < 2; mi++)
        offA[mi] = (uint32_t)((wm * 32 + mi * 16 + rowadd) * PITCH + coladd) * 4;
#pragma unroll
    for (int np = 0; np < 4; np++)
        offB[np] = (uint32_t)((wn * 64 + np * 16 + rowadd) * PITCH + coladd) * 4;

    float c[2][8][4];
#pragma unroll
    for (int mi = 0; mi < 2; mi++)
#pragma unroll
        for (int ni = 0; ni < 8; ni++)
#pragma unroll
            for (int q = 0; q < 4; q++) c[mi][ni][q] = 0.f;

    stage_logits(sA[0], sB[0], Ah, emb, mt, nt, 0, t);
    asm volatile("cp.async.commit_group;");
    stage_logits(sA[1], sB[1], Ah, emb, mt, nt, 32, t);
    asm volatile("cp.async.commit_group;");

    int buf = 0;
    for (int s = 0; s < 8; s++) {
        if (s + 2 < 8) {
            int nb = (buf + 2 >= NSTAGE) ? buf + 2 - NSTAGE : buf + 2;
            stage_logits(sA[nb], sB[nb], Ah, emb, mt, nt, (s + 2) * 32, t);
        }
        asm volatile("cp.async.commit_group;");
        asm volatile("cp.async.wait_group 2;");
        __syncthreads();
        uint32_t cA = sA[buf], cB = sB[buf];
#pragma unroll
        for (int ks = 0; ks < 32; ks += 8) {
            uint32_t a[2][4];
#pragma unroll
            for (int mi = 0; mi < 2; mi++) {
                asm volatile("ldmatrix.sync.aligned.m8n8.x4.shared.b16 {%0,%1,%2,%3}, [%4];"
                             : "=r"(a[mi][0]), "=r"(a[mi][1]), "=r"(a[mi][2]), "=r"(a[mi][3])
                             : "r"(cA + offA[mi] + (uint32_t)(ks * 4)));
            }
#pragma unroll
            for (int np = 0; np < 4; np++) {
                uint32_t b0, b1, b2, b3;
                asm volatile("ldmatrix.sync.aligned.m8n8.x4.shared.b16 {%0,%1,%2,%3}, [%4];"
                             : "=r"(b0), "=r"(b1), "=r"(b2), "=r"(b3)
                             : "r"(cB + offB[np] + (uint32_t)(ks * 4)));
#pragma unroll
                for (int mi = 0; mi < 2; mi++) {
                    mma_tf32(c[mi][2 * np],     a[mi][0], a[mi][1], a[mi][2], a[mi][3], b0, b2);
                    mma_tf32(c[mi][2 * np + 1], a[mi][0], a[mi][1], a[mi][2], a[mi][3], b1, b3);
                }
            }
        }
        __syncthreads();
        buf = (buf + 1 >= NSTAGE) ? 0 : buf + 1;
    }

    // ---- logits stores (c0/c1 -> row r0; c2/c3 -> row r0+8) ----
#pragma unroll
    for (int mi = 0; mi < 2; mi++) {
        int r0 = mt + wm * 32 + mi * 16 + g;
#pragma unroll
        for (int ni = 0; ni < 8; ni++) {
            int c0 = nt + wn * 64 + ni * 8 + 2 * tq;
            if (c0 < NM1) {
                out[(size_t)r0 * NM1 + c0]       = c[mi][ni][0];
                out[(size_t)(r0 + 8) * NM1 + c0] = c[mi][ni][2];
            }
            if (c0 + 1 < NM1) {
                out[(size_t)r0 * NM1 + c0 + 1]       = c[mi][ni][1];
                out[(size_t)(r0 + 8) * NM1 + c0 + 1] = c[mi][ni][3];
            }
        }
    }

    // ---- fused LSE partials: per-row (max, sumexp over this block's 128 cols) ----
    float* redM = smem;
    float* redS = smem + 256;
#pragma unroll
    for (int slot = 0; slot < 4; slot++) {
        int mi = slot >> 1, h = slot & 1;
        float m = -3.0e38f;
#pragma unroll
        for (int ni = 0; ni < 8; ni++) {
            int cbase = nt + wn * 64 + ni * 8 + 2 * tq;
            float v0 = (cbase     < NM1) ? c[mi][ni][2 * h]     : -3.0e38f;
            float v1 = (cbase + 1 < NM1) ? c[mi][ni][2 * h + 1] : -3.0e38f;
            m = fmaxf(m, fmaxf(v0, v1));
        }
        float sum = 0.f;
#pragma unroll
        for (int ni = 0; ni < 8; ni++) {
            int cbase = nt + wn * 64 + ni * 8 + 2 * tq;
            float v0 = (cbase     < NM1) ? c[mi][ni][2 * h]     : -3.0e38f;
            float v1 = (cbase + 1 < NM1) ? c[mi][ni][2 * h + 1] : -3.0e38f;
            sum += __expf(v0 - m) + __expf(v1 - m);
        }
#pragma unroll
        for (int off = 1; off <= 2; off <<= 1) {
            float m2 = __shfl_xor_sync(0xffffffffu, m, off);
            float s2 = __shfl_xor_sync(0xffffffffu, sum, off);
            float M = fmaxf(m, m2);
            sum = sum * __expf(m - M) + s2 * __expf(m2 - M);
            m = M;
        }
        if (tq == 0) {
            redM[(warp * 4 + slot) * 8 + g] = m;
            redS[(warp * 4 + slot) * 8 + g] = sum;
        }
    }
    __syncthreads();
    if (t < 128) {
        int wmr = t >> 5, slot = (t >> 3) & 3, gg = t & 7;
        int i1 = ((wmr * 2)     * 4 + slot) * 8 + gg;
        int i2 = ((wmr * 2 + 1) * 4 + slot) * 8 + gg;
        float m1 = redM[i1], s1 = redS[i1];
        float m2 = redM[i2], s2 = redS[i2];
        float M = fmaxf(m1, m2);
        float S = s1 * __expf(m1 - M) + s2 * __expf(m2 - M);
        int row = mt + wmr * 32 + (slot >> 1) * 16 + (slot & 1) * 8 + gg;
        g_pmax[(size_t)row * NBLK + blockIdx.y] = M;
        g_psum[(size_t)row * NBLK + blockIdx.y] = S;
    }
}

// ============================================================================
// K4: finalize LSE from per-block partials
// ============================================================================
__global__ void k_lsefin(float* __restrict__ lse) {
    int b = blockIdx.x, t = threadIdx.x;   // 256 threads
    float m = -3.0e38f, s = 0.f;
    for (int i = t; i < NBLK; i += 256) {
        float m2 = g_pmax[(size_t)b * NBLK + i];
        float s2 = g_psum[(size_t)b * NBLK + i];
        float M = fmaxf(m, m2);
        s = s * __expf(m - M) + s2 * __expf(m2 - M);
        m = M;
    }
    __shared__ float sm[256], ss[256];
    sm[t] = m; ss[t] = s;
    __syncthreads();
    for (int o = 128; o > 0; o >>= 1) {
        if (t < o) {
            float m2 = sm[t + o], s2 = ss[t + o];
            float M = fmaxf(sm[t], m2);
            ss[t] = ss[t] * __expf(sm[t] - M) + s2 * __expf(m2 - M);
            sm[t] = M;
        }
        __syncthreads();
    }
    if (t == 0) lse[b] = sm[0] + logf(ss[0]);
}

// ============================================================================
// K5: loss = -mean_b( logits[b, tar[b]-1] - lse[b] )
// ============================================================================
__global__ void k_loss(const float* __restrict__ logits, const float* __restrict__ lse,
                       const int* __restrict__ tar, float* __restrict__ loss_out) {
    __shared__ float red[512];
    int t = threadIdx.x;
    int tg = tar[t] - 1;
    red[t] = logits[(size_t)t * NM1 + tg] - lse[t];
    __syncthreads();
    for (int o = 256; o > 0; o >>= 1) {
        if (t < o) red[t] += red[t + o];
        __syncthreads();
    }
    if (t == 0) loss_out[0] = -red[0] / (float)BB;
}

// ============================================================================
// launch
// ============================================================================
extern "C" void kernel_launch(void* const* d_in, const int* in_sizes, int n_in,
                              void* d_out, int out_size) {
    const float* emb    = (const float*)d_in[0];
    const float* W1     = (const float*)d_in[1];
    const float* W2     = (const float*)d_in[2];
    const float* adjI   = (const float*)d_in[3];
    const float* adjO   = (const float*)d_in[4];
    const float* mask   = (const float*)d_in[5];
    const int*   item   = (const int*)d_in[6];
    const int*   alias_ = (const int*)d_in[7];
    const int*   tar    = (const int*)d_in[8];
    float* out = (float*)d_out;

    float *p_av, *p_h, *p_lh, *p_lse, *p_fb;
    cudaGetSymbolAddress((void**)&p_av,  g_avlast);
    cudaGetSymbolAddress((void**)&p_h,   g_h);
    cudaGetSymbolAddress((void**)&p_lh,  g_lasth);
    cudaGetSymbolAddress((void**)&p_lse, g_lse);
    cudaGetSymbolAddress((void**)&p_fb,  g_logits_fb);

    static int smem_set = 0;
    if (!smem_set) {
        cudaFuncSetAttribute(k_logits, cudaFuncAttributeMaxDynamicSharedMemorySize,
                             SMEM_LOGITS_BYTES);
        smem_set = 1;
    }

    const long long NL = (long long)BB * NM1;
    float *loss_ptr, *logits_ptr;
    if ((long long)out_size >= NL + 1)      { loss_ptr = out;  logits_ptr = out + 1; }
    else if ((long long)out_size == NL)     { loss_ptr = p_fb; logits_ptr = out; }
    else                                    { loss_ptr = out;  logits_ptr = p_fb; }

    k_avlast<<<BB, 256>>>(emb, adjI, adjO, mask, item, alias_);
    k_gemm<<<dim3(D2 / 32, BB / 64), 128>>>(p_av, W1, p_h,  BB, D2, D2, 1);  // relu(av@W1)
    k_gemm<<<dim3(DD / 32, BB / 64), 128>>>(p_h,  W2, p_lh, BB, D2, DD, 2);  // (h@W2) -> tf32
    k_logits<<<dim3(4, NBLK), 256, SMEM_LOGITS_BYTES>>>(p_lh, emb, logits_ptr);
    k_lsefin<<<BB, 256>>>(p_lse);
    k_loss<<<1, 512>>>(logits_ptr, p_lse, tar, loss_ptr);
}

// round 11
// speedup vs baseline: 1.5912x; 1.0054x over previous
#include <cuda_runtime.h>
#include <cstdint>

#define BB 512
#define SS 64
#define DD 256
#define NN 100000
#define NM1 99999
#define D2 512
#define NBLK 782            // ceil(99999/128)

// ---- scratch (device globals: no allocation allowed) ----
__device__ float g_avlast[BB * D2];
__device__ float g_h[BB * D2];
__device__ float g_lasth[BB * DD];
__device__ float g_lse[BB];
__device__ float g_pmax[BB * NBLK];
__device__ float g_psum[BB * NBLK];
__device__ float g_logits_fb[BB * NM1];

// ============================================================================
// K0: session length -> last id -> gather + dual adjacency row-aggregation
// ============================================================================
__global__ void k_avlast(const float* __restrict__ emb,
                         const float* __restrict__ adj_in,
                         const float* __restrict__ adj_out,
                         const float* __restrict__ mask,
                         const int* __restrict__ item,
                         const int* __restrict__ alias_) {
    int b = blockIdx.x, t = threadIdx.x;   // 256 threads
    __shared__ float ain[SS], aout[SS];
    __shared__ int items[SS];
    __shared__ int s_last;
    if (t == 0) {
        float s = 0.f;
        for (int i = 0; i < SS; i++) s += mask[b * SS + i];
        int rm = (int)s;
        s_last = alias_[b * SS + rm - 1];
    }
    __syncthreads();
    int last = s_last;
    if (t < SS) {
        ain[t]   = adj_in [((size_t)b * SS + last) * SS + t];
        aout[t]  = adj_out[((size_t)b * SS + last) * SS + t];
        items[t] = item[b * SS + t];
    }
    __syncthreads();
    int d = t;
    float aI = 0.f, aO = 0.f;
#pragma unroll 8
    for (int k = 0; k < SS; k++) {
        float e = emb[(size_t)items[k] * DD + d];
        aI = fmaf(ain[k],  e, aI);
        aO = fmaf(aout[k], e, aO);
    }
    g_avlast[b * D2 + d]      = aI;
    g_avlast[b * D2 + DD + d] = aO;
}

__device__ __forceinline__ uint32_t f2tf(float x) {
    uint32_t r;
    asm("cvt.rna.tf32.f32 %0, %1;" : "=r"(r) : "f"(x));
    return r;
}

// ============================================================================
// K1/K2: fp32 GEMM, 64(M)x32(N) tile, 128 threads, 4x4 micro-tile.
//        mode: 1 = relu epilogue, 2 = round output to tf32 (for MMA consumer)
// ============================================================================
__global__ __launch_bounds__(128) void k_gemm(const float* __restrict__ A,
                                              const float* __restrict__ Bm,
                                              float* __restrict__ C,
                                              int M, int K, int N, int mode) {
    __shared__ float As[16][68];
    __shared__ float Bs[16][36];
    int t = threadIdx.x;
    int tx = t & 7, ty = t >> 3;
    int row0 = blockIdx.y * 64, col0 = blockIdx.x * 32;

    int ra = t >> 2, ka = (t & 3) << 2;
    int kb = t >> 3, cb = (t & 7) << 2;
    const float* pA0 = A + (size_t)(row0 + ra) * K + ka;
    const float* pA1 = A + (size_t)(row0 + ra + 32) * K + ka;
    const float* pB  = Bm + (size_t)kb * N + col0 + cb;

    float4 fa0 = *(const float4*)pA0;
    float4 fa1 = *(const float4*)pA1;
    float4 fb  = *(const float4*)pB;

    float acc[4][4] = {};
    for (int k0 = 0; k0 < K; k0 += 16) {
        As[ka][ra]           = fa0.x; As[ka + 1][ra]      = fa0.y;
        As[ka + 2][ra]       = fa0.z; As[ka + 3][ra]      = fa0.w;
        As[ka][ra + 32]      = fa1.x; As[ka + 1][ra + 32] = fa1.y;
        As[ka + 2][ra + 32]  = fa1.z; As[ka + 3][ra + 32] = fa1.w;
        *(float4*)&Bs[kb][cb] = fb;
        __syncthreads();
        if (k0 + 16 < K) {
            fa0 = *(const float4*)(pA0 + k0 + 16);
            fa1 = *(const float4*)(pA1 + k0 + 16);
            fb  = *(const float4*)(pB + (size_t)(k0 + 16) * N);
        }
#pragma unroll
        for (int kk = 0; kk < 16; kk++) {
            float4 a = *(float4*)&As[kk][ty * 4];
            float4 b = *(float4*)&Bs[kk][tx * 4];
            float av[4] = {a.x, a.y, a.z, a.w};
            float bv[4] = {b.x, b.y, b.z, b.w};
#pragma unroll
            for (int i = 0; i < 4; i++)
#pragma unroll
                for (int j = 0; j < 4; j++)
                    acc[i][j] = fmaf(av[i], bv[j], acc[i][j]);
        }
        __syncthreads();
    }
#pragma unroll
    for (int i = 0; i < 4; i++) {
        float4 v;
        float* vp = &v.x;
#pragma unroll
        for (int j = 0; j < 4; j++) {
            float x = acc[i][j];
            if (mode == 1) x = fmaxf(x, 0.f);
            if (mode == 2) x = __uint_as_float(f2tf(x));
            vp[j] = x;
        }
        *(float4*)&C[(size_t)(row0 + ty * 4 + i) * N + col0 + tx * 4] = v;
    }
}

// ============================================================================
// K3: logits[512,99999] = last_h[512,256] @ emb[1:].T  (TF32 mma.sync)
//     128x128 tile, 8 warps (4M x 2N), K-chunk 32, 3-buffer pipeline with
//     mbarrier flow control (NO __syncthreads in mainloop):
//       full[b]: count 256, fired by cp.async.mbarrier.arrive.noinc
//       empty[b]: count 8, per-warp arrive after consuming buffer b
//     Warps run decoupled with ~1 chunk of slack. ldmatrix.x4 fragments,
//     fused per-row (max, sumexp) partials.
// ============================================================================
__device__ __forceinline__ void mma_tf32(float* c, uint32_t a0, uint32_t a1,
                                         uint32_t a2, uint32_t a3,
                                         uint32_t b0, uint32_t b1) {
    asm volatile("mma.sync.aligned.m16n8k8.row.col.f32.tf32.tf32.f32 "
                 "{%0,%1,%2,%3},{%4,%5,%6,%7},{%8,%9},{%0,%1,%2,%3};"
                 : "+f"(c[0]), "+f"(c[1]), "+f"(c[2]), "+f"(c[3])
                 : "r"(a0), "r"(a1), "r"(a2), "r"(a3), "r"(b0), "r"(b1));
}

__device__ __forceinline__ void mbar_wait(uint32_t addr, uint32_t parity) {
    asm volatile(
        "{\n\t.reg .pred P;\n\t"
        "WL%=:\n\t"
        "mbarrier.try_wait.parity.acquire.cta.shared::cta.b64 P, [%0], %1, 0x989680;\n\t"
        "@P bra.uni DN%=;\n\t"
        "bra.uni WL%=;\n\t"
        "DN%=:\n\t}"
        :: "r"(addr), "r"(parity) : "memory");
}

#define PITCH 36                       // words per smem row (144B, conflict-free LDSM)
#define STG_W (128 * PITCH)            // words per stage matrix (18432 B)
#define NST 3
#define NCHUNK 8
#define SM_CTRL 1024
#define SMEM_LOGITS_BYTES (SM_CTRL + 2 * NST * STG_W * 4)   // 111616 B

__device__ __forceinline__ void stage_logits(uint32_t sA, uint32_t sB,
                                             const float* __restrict__ Ah,
                                             const float* __restrict__ emb,
                                             int mt, int nt, int k0, int t) {
#pragma unroll
    for (int u0 = 0; u0 < 4; u0++) {
        int u = t + u0 * 256;
        int r = u >> 3, c = (u & 7) << 2;       // c in floats (16B chunks)
        uint32_t da = sA + (uint32_t)(r * PITCH + c) * 4;
        const float* srcA = Ah + (size_t)(mt + r) * DD + k0 + c;
        asm volatile("cp.async.cg.shared.global [%0], [%1], 16;\n"
                     :: "r"(da), "l"(srcA));
        int er = nt + 1 + r;
        uint32_t db = sB + (uint32_t)(r * PITCH + c) * 4;
        const float* srcB = emb + (size_t)(er < NN ? er : 0) * DD + k0 + c;
        int sz = (er < NN) ? 16 : 0;
        asm volatile("cp.async.cg.shared.global [%0], [%1], 16, %2;\n"
                     :: "r"(db), "l"(srcB), "r"(sz));
    }
}

__global__ __launch_bounds__(256) void k_logits(const float* __restrict__ Ah,
                                                const float* __restrict__ emb,
                                                float* __restrict__ out) {
    extern __shared__ float smem[];
    uint32_t sbase = (uint32_t)__cvta_generic_to_shared(smem);
    // control region: full[i] at sbase+16*i, empty[i] at sbase+16*i+8
    uint32_t mfull[NST], mempty[NST];
#pragma unroll
    for (int i = 0; i < NST; i++) { mfull[i] = sbase + 16 * i; mempty[i] = sbase + 16 * i + 8; }
    const uint32_t ASZ = STG_W * 4;
    uint32_t sA[NST], sB[NST];
#pragma unroll
    for (int i = 0; i < NST; i++) {
        sA[i] = sbase + SM_CTRL + i * ASZ;
        sB[i] = sbase + SM_CTRL + (NST + i) * ASZ;
    }

    int mt = blockIdx.x * 128;
    int nt = blockIdx.y * 128;
    int t = threadIdx.x;
    int warp = t >> 5, lane = t & 31;
    int wm = warp >> 1, wn = warp & 1;
    int g = lane >> 2, tq = lane & 3;
    int lr = lane & 7, bq = lane >> 3;
    int rowadd = lr + ((bq & 1) << 3);
    int coladd = (bq >> 1) << 2;

    uint32_t offA[2], offB[4];
#pragma unroll
    for (int mi = 0; mi < 2; mi++)
        offA[mi] = (uint32_t)((wm * 32 + mi * 16 + rowadd) * PITCH + coladd) * 4;
#pragma unroll
    for (int np = 0; np < 4; np++)
        offB[np] = (uint32_t)((wn * 64 + np * 16 + rowadd) * PITCH + coladd) * 4;

    float c[2][8][4];
#pragma unroll
    for (int mi = 0; mi < 2; mi++)
#pragma unroll
        for (int ni = 0; ni < 8; ni++)
#pragma unroll
            for (int q = 0; q < 4; q++) c[mi][ni][q] = 0.f;

    if (t == 0) {
#pragma unroll
        for (int i = 0; i < NST; i++) {
            asm volatile("mbarrier.init.shared.b64 [%0], 256;" :: "r"(mfull[i])  : "memory");
            asm volatile("mbarrier.init.shared.b64 [%0], 8;"   :: "r"(mempty[i]) : "memory");
        }
    }
    __syncthreads();

    // prologue: stage chunks 0,1 (async-arrive fires full[b] when copies land)
    stage_logits(sA[0], sB[0], Ah, emb, mt, nt, 0, t);
    asm volatile("cp.async.mbarrier.arrive.noinc.shared.b64 [%0];" :: "r"(mfull[0]) : "memory");
    stage_logits(sA[1], sB[1], Ah, emb, mt, nt, 32, t);
    asm volatile("cp.async.mbarrier.arrive.noinc.shared.b64 [%0];" :: "r"(mfull[1]) : "memory");

    for (int s = 0; s < NCHUNK; s++) {
        // ---- producer: stage chunk u = s+2 (buffer reused from chunk u-3) ----
        int u = s + 2;
        if (u < NCHUNK) {
            int b2 = u % NST;
            if (u >= NST)   // wait for all 8 warps to finish consuming chunk u-3
                mbar_wait(mempty[b2], (uint32_t)(((u - NST) / NST) & 1));
            stage_logits(sA[b2], sB[b2], Ah, emb, mt, nt, u * 32, t);
            asm volatile("cp.async.mbarrier.arrive.noinc.shared.b64 [%0];"
                         :: "r"(mfull[b2]) : "memory");
        }
        // ---- consumer: chunk s ----
        int b = s % NST;
        mbar_wait(mfull[b], (uint32_t)((s / NST) & 1));
        uint32_t cA = sA[b], cB = sB[b];
#pragma unroll
        for (int ks = 0; ks < 32; ks += 8) {
            uint32_t a[2][4];
#pragma unroll
            for (int mi = 0; mi < 2; mi++) {
                asm volatile("ldmatrix.sync.aligned.m8n8.x4.shared.b16 {%0,%1,%2,%3}, [%4];"
                             : "=r"(a[mi][0]), "=r"(a[mi][1]), "=r"(a[mi][2]), "=r"(a[mi][3])
                             : "r"(cA + offA[mi] + (uint32_t)(ks * 4)));
            }
#pragma unroll
            for (int np = 0; np < 4; np++) {
                uint32_t b0, b1, b2r, b3;
                asm volatile("ldmatrix.sync.aligned.m8n8.x4.shared.b16 {%0,%1,%2,%3}, [%4];"
                             : "=r"(b0), "=r"(b1), "=r"(b2r), "=r"(b3)
                             : "r"(cB + offB[np] + (uint32_t)(ks * 4)));
#pragma unroll
                for (int mi = 0; mi < 2; mi++) {
                    mma_tf32(c[mi][2 * np],     a[mi][0], a[mi][1], a[mi][2], a[mi][3], b0, b2r);
                    mma_tf32(c[mi][2 * np + 1], a[mi][0], a[mi][1], a[mi][2], a[mi][3], b1, b3);
                }
            }
        }
        if (lane == 0)
            asm volatile("mbarrier.arrive.shared.b64 _, [%0];" :: "r"(mempty[b]) : "memory");
    }

    // ---- logits stores (c0/c1 -> row r0; c2/c3 -> row r0+8) ----
#pragma unroll
    for (int mi = 0; mi < 2; mi++) {
        int r0 = mt + wm * 32 + mi * 16 + g;
#pragma unroll
        for (int ni = 0; ni < 8; ni++) {
            int c0 = nt + wn * 64 + ni * 8 + 2 * tq;
            if (c0 < NM1) {
                out[(size_t)r0 * NM1 + c0]       = c[mi][ni][0];
                out[(size_t)(r0 + 8) * NM1 + c0] = c[mi][ni][2];
            }
            if (c0 + 1 < NM1) {
                out[(size_t)r0 * NM1 + c0 + 1]       = c[mi][ni][1];
                out[(size_t)(r0 + 8) * NM1 + c0 + 1] = c[mi][ni][3];
            }
        }
    }

    // all warps must be done with stage buffers before smem reuse below
    __syncthreads();

    // ---- fused LSE partials: per-row (max, sumexp over this block's 128 cols) ----
    float* redM = smem + 256;       // reuse stage buffer area (bytes 1024+)
    float* redS = smem + 512;
#pragma unroll
    for (int slot = 0; slot < 4; slot++) {
        int mi = slot >> 1, h = slot & 1;
        float m = -3.0e38f;
#pragma unroll
        for (int ni = 0; ni < 8; ni++) {
            int cbase = nt + wn * 64 + ni * 8 + 2 * tq;
            float v0 = (cbase     < NM1) ? c[mi][ni][2 * h]     : -3.0e38f;
            float v1 = (cbase + 1 < NM1) ? c[mi][ni][2 * h + 1] : -3.0e38f;
            m = fmaxf(m, fmaxf(v0, v1));
        }
        float sum = 0.f;
#pragma unroll
        for (int ni = 0; ni < 8; ni++) {
            int cbase = nt + wn * 64 + ni * 8 + 2 * tq;
            float v0 = (cbase     < NM1) ? c[mi][ni][2 * h]     : -3.0e38f;
            float v1 = (cbase + 1 < NM1) ? c[mi][ni][2 * h + 1] : -3.0e38f;
            sum += __expf(v0 - m) + __expf(v1 - m);
        }
#pragma unroll
        for (int off = 1; off <= 2; off <<= 1) {
            float m2 = __shfl_xor_sync(0xffffffffu, m, off);
            float s2 = __shfl_xor_sync(0xffffffffu, sum, off);
            float M = fmaxf(m, m2);
            sum = sum * __expf(m - M) + s2 * __expf(m2 - M);
            m = M;
        }
        if (tq == 0) {
            redM[(warp * 4 + slot) * 8 + g] = m;
            redS[(warp * 4 + slot) * 8 + g] = sum;
        }
    }
    __syncthreads();
    if (t < 128) {
        int wmr = t >> 5, slot = (t >> 3) & 3, gg = t & 7;
        int i1 = ((wmr * 2)     * 4 + slot) * 8 + gg;
        int i2 = ((wmr * 2 + 1) * 4 + slot) * 8 + gg;
        float m1 = redM[i1], s1 = redS[i1];
        float m2 = redM[i2], s2 = redS[i2];
        float M = fmaxf(m1, m2);
        float S = s1 * __expf(m1 - M) + s2 * __expf(m2 - M);
        int row = mt + wmr * 32 + (slot >> 1) * 16 + (slot & 1) * 8 + gg;
        g_pmax[(size_t)row * NBLK + blockIdx.y] = M;
        g_psum[(size_t)row * NBLK + blockIdx.y] = S;
    }
}

// ============================================================================
// K4: finalize LSE from per-block partials
// ============================================================================
__global__ void k_lsefin(float* __restrict__ lse) {
    int b = blockIdx.x, t = threadIdx.x;   // 256 threads
    float m = -3.0e38f, s = 0.f;
    for (int i = t; i < NBLK; i += 256) {
        float m2 = g_pmax[(size_t)b * NBLK + i];
        float s2 = g_psum[(size_t)b * NBLK + i];
        float M = fmaxf(m, m2);
        s = s * __expf(m - M) + s2 * __expf(m2 - M);
        m = M;
    }
    __shared__ float sm[256], ss[256];
    sm[t] = m; ss[t] = s;
    __syncthreads();
    for (int o = 128; o > 0; o >>= 1) {
        if (t < o) {
            float m2 = sm[t + o], s2 = ss[t + o];
            float M = fmaxf(sm[t], m2);
            ss[t] = ss[t] * __expf(sm[t] - M) + s2 * __expf(m2 - M);
            sm[t] = M;
        }
        __syncthreads();
    }
    if (t == 0) lse[b] = sm[0] + logf(ss[0]);
}

// ============================================================================
// K5: loss = -mean_b( logits[b, tar[b]-1] - lse[b] )
// ============================================================================
__global__ void k_loss(const float* __restrict__ logits, const float* __restrict__ lse,
                       const int* __restrict__ tar, float* __restrict__ loss_out) {
    __shared__ float red[512];
    int t = threadIdx.x;
    int tg = tar[t] - 1;
    red[t] = logits[(size_t)t * NM1 + tg] - lse[t];
    __syncthreads();
    for (int o = 256; o > 0; o >>= 1) {
        if (t < o) red[t] += red[t + o];
        __syncthreads();
    }
    if (t == 0) loss_out[0] = -red[0] / (float)BB;
}

// ============================================================================
// launch
// ============================================================================
extern "C" void kernel_launch(void* const* d_in, const int* in_sizes, int n_in,
                              void* d_out, int out_size) {
    const float* emb    = (const float*)d_in[0];
    const float* W1     = (const float*)d_in[1];
    const float* W2     = (const float*)d_in[2];
    const float* adjI   = (const float*)d_in[3];
    const float* adjO   = (const float*)d_in[4];
    const float* mask   = (const float*)d_in[5];
    const int*   item   = (const int*)d_in[6];
    const int*   alias_ = (const int*)d_in[7];
    const int*   tar    = (const int*)d_in[8];
    float* out = (float*)d_out;

    float *p_av, *p_h, *p_lh, *p_lse, *p_fb;
    cudaGetSymbolAddress((void**)&p_av,  g_avlast);
    cudaGetSymbolAddress((void**)&p_h,   g_h);
    cudaGetSymbolAddress((void**)&p_lh,  g_lasth);
    cudaGetSymbolAddress((void**)&p_lse, g_lse);
    cudaGetSymbolAddress((void**)&p_fb,  g_logits_fb);

    static int smem_set = 0;
    if (!smem_set) {
        cudaFuncSetAttribute(k_logits, cudaFuncAttributeMaxDynamicSharedMemorySize,
                             SMEM_LOGITS_BYTES);
        smem_set = 1;
    }

    const long long NL = (long long)BB * NM1;
    float *loss_ptr, *logits_ptr;
    if ((long long)out_size >= NL + 1)      { loss_ptr = out;  logits_ptr = out + 1; }
    else if ((long long)out_size == NL)     { loss_ptr = p_fb; logits_ptr = out; }
    else                                    { loss_ptr = out;  logits_ptr = p_fb; }

    k_avlast<<<BB, 256>>>(emb, adjI, adjO, mask, item, alias_);
    k_gemm<<<dim3(D2 / 32, BB / 64), 128>>>(p_av, W1, p_h,  BB, D2, D2, 1);  // relu(av@W1)
    k_gemm<<<dim3(DD / 32, BB / 64), 128>>>(p_h,  W2, p_lh, BB, D2, DD, 2);  // (h@W2) -> tf32
    k_logits<<<dim3(4, NBLK), 256, SMEM_LOGITS_BYTES>>>(p_lh, emb, logits_ptr);
    k_lsefin<<<BB, 256>>>(p_lse);
    k_loss<<<1, 512>>>(logits_ptr, p_lse, tar, loss_ptr);
}

// round 12
// speedup vs baseline: 1.8897x; 1.1876x over previous
#include <cuda_runtime.h>
#include <cuda_fp16.h>
#include <cstdint>

#define BB 512
#define SS 64
#define DD 256
#define NN 100000
#define NM1 99999
#define D2 512
#define NBLK 782            // ceil(99999/128)

// ---- scratch (device globals: no allocation allowed) ----
__device__ float  g_avlast[BB * D2];
__device__ float  g_h[BB * D2];
__device__ __half g_lasth_h[BB * DD];
__device__ __half g_emb_h[NN * DD];          // fp16 copy of embedding (51.2 MB)
__device__ float  g_lse[BB];
__device__ float  g_pmax[BB * NBLK];
__device__ float  g_psum[BB * NBLK];
__device__ float  g_logits_fb[BB * NM1];

// ============================================================================
// K-1: convert embedding fp32 -> fp16 (grid-stride float4 -> half2 x2)
// ============================================================================
__global__ void k_cvt(const float* __restrict__ src, __half* __restrict__ dst, int n4) {
    int i = blockIdx.x * blockDim.x + threadIdx.x;
    int stride = gridDim.x * blockDim.x;
    const float4* s4 = (const float4*)src;
    __half2* d2 = (__half2*)dst;
    for (; i < n4; i += stride) {
        float4 v = s4[i];
        d2[2 * i]     = __floats2half2_rn(v.x, v.y);
        d2[2 * i + 1] = __floats2half2_rn(v.z, v.w);
    }
}

// ============================================================================
// K0: session length -> last id -> gather + dual adjacency row-aggregation
// ============================================================================
__global__ void k_avlast(const float* __restrict__ emb,
                         const float* __restrict__ adj_in,
                         const float* __restrict__ adj_out,
                         const float* __restrict__ mask,
                         const int* __restrict__ item,
                         const int* __restrict__ alias_) {
    int b = blockIdx.x, t = threadIdx.x;   // 256 threads
    __shared__ float ain[SS], aout[SS];
    __shared__ int items[SS];
    __shared__ int s_last;
    if (t == 0) {
        float s = 0.f;
        for (int i = 0; i < SS; i++) s += mask[b * SS + i];
        int rm = (int)s;
        s_last = alias_[b * SS + rm - 1];
    }
    __syncthreads();
    int last = s_last;
    if (t < SS) {
        ain[t]   = adj_in [((size_t)b * SS + last) * SS + t];
        aout[t]  = adj_out[((size_t)b * SS + last) * SS + t];
        items[t] = item[b * SS + t];
    }
    __syncthreads();
    int d = t;
    float aI = 0.f, aO = 0.f;
#pragma unroll 8
    for (int k = 0; k < SS; k++) {
        float e = emb[(size_t)items[k] * DD + d];
        aI = fmaf(ain[k],  e, aI);
        aO = fmaf(aout[k], e, aO);
    }
    g_avlast[b * D2 + d]      = aI;
    g_avlast[b * D2 + DD + d] = aO;
}

// ============================================================================
// K1/K2: fp32 GEMM, 64(M)x32(N) tile, 128 threads, 4x4 micro-tile.
//        mode: 1 = relu epilogue (fp32 out), 2 = fp16 output (for MMA consumer)
// ============================================================================
__global__ __launch_bounds__(128) void k_gemm(const float* __restrict__ A,
                                              const float* __restrict__ Bm,
                                              float* __restrict__ C,
                                              int M, int K, int N, int mode) {
    __shared__ float As[16][68];
    __shared__ float Bs[16][36];
    int t = threadIdx.x;
    int tx = t & 7, ty = t >> 3;
    int row0 = blockIdx.y * 64, col0 = blockIdx.x * 32;

    int ra = t >> 2, ka = (t & 3) << 2;
    int kb = t >> 3, cb = (t & 7) << 2;
    const float* pA0 = A + (size_t)(row0 + ra) * K + ka;
    const float* pA1 = A + (size_t)(row0 + ra + 32) * K + ka;
    const float* pB  = Bm + (size_t)kb * N + col0 + cb;

    float4 fa0 = *(const float4*)pA0;
    float4 fa1 = *(const float4*)pA1;
    float4 fb  = *(const float4*)pB;

    float acc[4][4] = {};
    for (int k0 = 0; k0 < K; k0 += 16) {
        As[ka][ra]           = fa0.x; As[ka + 1][ra]      = fa0.y;
        As[ka + 2][ra]       = fa0.z; As[ka + 3][ra]      = fa0.w;
        As[ka][ra + 32]      = fa1.x; As[ka + 1][ra + 32] = fa1.y;
        As[ka + 2][ra + 32]  = fa1.z; As[ka + 3][ra + 32] = fa1.w;
        *(float4*)&Bs[kb][cb] = fb;
        __syncthreads();
        if (k0 + 16 < K) {
            fa0 = *(const float4*)(pA0 + k0 + 16);
            fa1 = *(const float4*)(pA1 + k0 + 16);
            fb  = *(const float4*)(pB + (size_t)(k0 + 16) * N);
        }
#pragma unroll
        for (int kk = 0; kk < 16; kk++) {
            float4 a = *(float4*)&As[kk][ty * 4];
            float4 b = *(float4*)&Bs[kk][tx * 4];
            float av[4] = {a.x, a.y, a.z, a.w};
            float bv[4] = {b.x, b.y, b.z, b.w};
#pragma unroll
            for (int i = 0; i < 4; i++)
#pragma unroll
                for (int j = 0; j < 4; j++)
                    acc[i][j] = fmaf(av[i], bv[j], acc[i][j]);
        }
        __syncthreads();
    }
    if (mode == 2) {
        __half* Ch = (__half*)C;
#pragma unroll
        for (int i = 0; i < 4; i++) {
            __half2 h01 = __floats2half2_rn(acc[i][0], acc[i][1]);
            __half2 h23 = __floats2half2_rn(acc[i][2], acc[i][3]);
            __half2* dst = (__half2*)&Ch[(size_t)(row0 + ty * 4 + i) * N + col0 + tx * 4];
            dst[0] = h01; dst[1] = h23;
        }
    } else {
#pragma unroll
        for (int i = 0; i < 4; i++) {
            float4 v;
            v.x = fmaxf(acc[i][0], 0.f); v.y = fmaxf(acc[i][1], 0.f);
            v.z = fmaxf(acc[i][2], 0.f); v.w = fmaxf(acc[i][3], 0.f);
            *(float4*)&C[(size_t)(row0 + ty * 4 + i) * N + col0 + tx * 4] = v;
        }
    }
}

// ============================================================================
// K3: logits[512,99999] = last_h[512,256] @ emb[1:].T  (FP16 mma m16n8k16)
//     128x128 tile, 8 warps (4M x 2N), K-chunk 64 halves (128B rows),
//     3-buffer mbarrier pipeline, ldmatrix.x4 fragments, fused LSE partials.
// ============================================================================
__device__ __forceinline__ void mma_f16(float* c, uint32_t a0, uint32_t a1,
                                        uint32_t a2, uint32_t a3,
                                        uint32_t b0, uint32_t b1) {
    asm volatile("mma.sync.aligned.m16n8k16.row.col.f32.f16.f16.f32 "
                 "{%0,%1,%2,%3},{%4,%5,%6,%7},{%8,%9},{%0,%1,%2,%3};"
                 : "+f"(c[0]), "+f"(c[1]), "+f"(c[2]), "+f"(c[3])
                 : "r"(a0), "r"(a1), "r"(a2), "r"(a3), "r"(b0), "r"(b1));
}

__device__ __forceinline__ void mbar_wait(uint32_t addr, uint32_t parity) {
    asm volatile(
        "{\n\t.reg .pred P;\n\t"
        "WL%=:\n\t"
        "mbarrier.try_wait.parity.acquire.cta.shared::cta.b64 P, [%0], %1, 0x989680;\n\t"
        "@P bra.uni DN%=;\n\t"
        "bra.uni WL%=;\n\t"
        "DN%=:\n\t}"
        :: "r"(addr), "r"(parity) : "memory");
}

#define PITCHB 144                     // bytes per smem row (conflict-free LDSM)
#define STG_B (128 * PITCHB)           // bytes per stage matrix (18432)
#define NST 3
#define NCHUNK 4                       // 256 K-halves / 64 per chunk
#define SM_CTRL 1024
#define SMEM_LOGITS_BYTES (SM_CTRL + 2 * NST * STG_B)   // 111616 B

// stage chunk k0 (in halves) of A (last_h) and B (emb_h) tiles; 128B/row
__device__ __forceinline__ void stage_logits(uint32_t sA, uint32_t sB,
                                             const __half* __restrict__ Ah,
                                             const __half* __restrict__ embh,
                                             int mt, int nt, int k0, int t) {
#pragma unroll
    for (int u0 = 0; u0 < 4; u0++) {
        int u = t + u0 * 256;
        int r = u >> 3, c16 = u & 7;            // row, 16B chunk (8 halves)
        uint32_t da = sA + (uint32_t)(r * PITCHB + c16 * 16);
        const __half* srcA = Ah + (size_t)(mt + r) * DD + k0 + c16 * 8;
        asm volatile("cp.async.cg.shared.global [%0], [%1], 16;\n"
                     :: "r"(da), "l"(srcA));
        int er = nt + 1 + r;
        uint32_t db = sB + (uint32_t)(r * PITCHB + c16 * 16);
        const __half* srcB = embh + (size_t)(er < NN ? er : 0) * DD + k0 + c16 * 8;
        int sz = (er < NN) ? 16 : 0;
        asm volatile("cp.async.cg.shared.global [%0], [%1], 16, %2;\n"
                     :: "r"(db), "l"(srcB), "r"(sz));
    }
}

__global__ __launch_bounds__(256) void k_logits(const __half* __restrict__ Ah,
                                                const __half* __restrict__ embh,
                                                float* __restrict__ out) {
    extern __shared__ float smem[];
    uint32_t sbase = (uint32_t)__cvta_generic_to_shared(smem);
    uint32_t mfull[NST], mempty[NST];
#pragma unroll
    for (int i = 0; i < NST; i++) { mfull[i] = sbase + 16 * i; mempty[i] = sbase + 16 * i + 8; }
    uint32_t sA[NST], sB[NST];
#pragma unroll
    for (int i = 0; i < NST; i++) {
        sA[i] = sbase + SM_CTRL + i * STG_B;
        sB[i] = sbase + SM_CTRL + (NST + i) * STG_B;
    }

    int mt = blockIdx.x * 128;
    int nt = blockIdx.y * 128;
    int t = threadIdx.x;
    int warp = t >> 5, lane = t & 31;
    int wm = warp >> 1, wn = warp & 1;
    int g = lane >> 2, tq = lane & 3;
    int lr = lane & 7, bq = lane >> 3;
    int rowadd = lr + ((bq & 1) << 3);
    int coladdB = (bq >> 1) << 4;      // 0 or 16 bytes (k-halves 0-7 / 8-15)

    uint32_t offA[2], offB[4];
#pragma unroll
    for (int mi = 0; mi < 2; mi++)
        offA[mi] = (uint32_t)((wm * 32 + mi * 16 + rowadd) * PITCHB + coladdB);
#pragma unroll
    for (int np = 0; np < 4; np++)
        offB[np] = (uint32_t)((wn * 64 + np * 16 + rowadd) * PITCHB + coladdB);

    float c[2][8][4];
#pragma unroll
    for (int mi = 0; mi < 2; mi++)
#pragma unroll
        for (int ni = 0; ni < 8; ni++)
#pragma unroll
            for (int q = 0; q < 4; q++) c[mi][ni][q] = 0.f;

    if (t == 0) {
#pragma unroll
        for (int i = 0; i < NST; i++) {
            asm volatile("mbarrier.init.shared.b64 [%0], 256;" :: "r"(mfull[i])  : "memory");
            asm volatile("mbarrier.init.shared.b64 [%0], 8;"   :: "r"(mempty[i]) : "memory");
        }
    }
    __syncthreads();

    // prologue: stage chunks 0,1
    stage_logits(sA[0], sB[0], Ah, embh, mt, nt, 0, t);
    asm volatile("cp.async.mbarrier.arrive.noinc.shared.b64 [%0];" :: "r"(mfull[0]) : "memory");
    stage_logits(sA[1], sB[1], Ah, embh, mt, nt, 64, t);
    asm volatile("cp.async.mbarrier.arrive.noinc.shared.b64 [%0];" :: "r"(mfull[1]) : "memory");

    for (int s = 0; s < NCHUNK; s++) {
        int u = s + 2;
        if (u < NCHUNK) {
            int b2 = u % NST;
            if (u >= NST)
                mbar_wait(mempty[b2], (uint32_t)(((u - NST) / NST) & 1));
            stage_logits(sA[b2], sB[b2], Ah, embh, mt, nt, u * 64, t);
            asm volatile("cp.async.mbarrier.arrive.noinc.shared.b64 [%0];"
                         :: "r"(mfull[b2]) : "memory");
        }
        int b = s % NST;
        mbar_wait(mfull[b], (uint32_t)((s / NST) & 1));
        uint32_t cA = sA[b], cB = sB[b];
#pragma unroll
        for (int ks = 0; ks < 4; ks++) {       // 4 x K16 steps per 64-half chunk
            uint32_t kb = (uint32_t)(ks * 32); // 16 halves = 32 bytes
            uint32_t a[2][4];
#pragma unroll
            for (int mi = 0; mi < 2; mi++) {
                asm volatile("ldmatrix.sync.aligned.m8n8.x4.shared.b16 {%0,%1,%2,%3}, [%4];"
                             : "=r"(a[mi][0]), "=r"(a[mi][1]), "=r"(a[mi][2]), "=r"(a[mi][3])
                             : "r"(cA + offA[mi] + kb));
            }
#pragma unroll
            for (int np = 0; np < 4; np++) {
                uint32_t b0, b1, b2r, b3;
                asm volatile("ldmatrix.sync.aligned.m8n8.x4.shared.b16 {%0,%1,%2,%3}, [%4];"
                             : "=r"(b0), "=r"(b1), "=r"(b2r), "=r"(b3)
                             : "r"(cB + offB[np] + kb));
#pragma unroll
                for (int mi = 0; mi < 2; mi++) {
                    mma_f16(c[mi][2 * np],     a[mi][0], a[mi][1], a[mi][2], a[mi][3], b0, b2r);
                    mma_f16(c[mi][2 * np + 1], a[mi][0], a[mi][1], a[mi][2], a[mi][3], b1, b3);
                }
            }
        }
        if (lane == 0)
            asm volatile("mbarrier.arrive.shared.b64 _, [%0];" :: "r"(mempty[b]) : "memory");
    }

    // ---- logits stores (c0/c1 -> row r0; c2/c3 -> row r0+8) ----
#pragma unroll
    for (int mi = 0; mi < 2; mi++) {
        int r0 = mt + wm * 32 + mi * 16 + g;
#pragma unroll
        for (int ni = 0; ni < 8; ni++) {
            int c0 = nt + wn * 64 + ni * 8 + 2 * tq;
            if (c0 < NM1) {
                out[(size_t)r0 * NM1 + c0]       = c[mi][ni][0];
                out[(size_t)(r0 + 8) * NM1 + c0] = c[mi][ni][2];
            }
            if (c0 + 1 < NM1) {
                out[(size_t)r0 * NM1 + c0 + 1]       = c[mi][ni][1];
                out[(size_t)(r0 + 8) * NM1 + c0 + 1] = c[mi][ni][3];
            }
        }
    }

    __syncthreads();   // stage buffers dead; safe to reuse smem

    // ---- fused LSE partials: per-row (max, sumexp over this block's 128 cols) ----
    float* redM = smem + 256;
    float* redS = smem + 512;
#pragma unroll
    for (int slot = 0; slot < 4; slot++) {
        int mi = slot >> 1, h = slot & 1;
        float m = -3.0e38f;
#pragma unroll
        for (int ni = 0; ni < 8; ni++) {
            int cbase = nt + wn * 64 + ni * 8 + 2 * tq;
            float v0 = (cbase     < NM1) ? c[mi][ni][2 * h]     : -3.0e38f;
            float v1 = (cbase + 1 < NM1) ? c[mi][ni][2 * h + 1] : -3.0e38f;
            m = fmaxf(m, fmaxf(v0, v1));
        }
        float sum = 0.f;
#pragma unroll
        for (int ni = 0; ni < 8; ni++) {
            int cbase = nt + wn * 64 + ni * 8 + 2 * tq;
            float v0 = (cbase     < NM1) ? c[mi][ni][2 * h]     : -3.0e38f;
            float v1 = (cbase + 1 < NM1) ? c[mi][ni][2 * h + 1] : -3.0e38f;
            sum += __expf(v0 - m) + __expf(v1 - m);
        }
#pragma unroll
        for (int off = 1; off <= 2; off <<= 1) {
            float m2 = __shfl_xor_sync(0xffffffffu, m, off);
            float s2 = __shfl_xor_sync(0xffffffffu, sum, off);
            float M = fmaxf(m, m2);
            sum = sum * __expf(m - M) + s2 * __expf(m2 - M);
            m = M;
        }
        if (tq == 0) {
            redM[(warp * 4 + slot) * 8 + g] = m;
            redS[(warp * 4 + slot) * 8 + g] = sum;
        }
    }
    __syncthreads();
    if (t < 128) {
        int wmr = t >> 5, slot = (t >> 3) & 3, gg = t & 7;
        int i1 = ((wmr * 2)     * 4 + slot) * 8 + gg;
        int i2 = ((wmr * 2 + 1) * 4 + slot) * 8 + gg;
        float m1 = redM[i1], s1 = redS[i1];
        float m2 = redM[i2], s2 = redS[i2];
        float M = fmaxf(m1, m2);
        float S = s1 * __expf(m1 - M) + s2 * __expf(m2 - M);
        int row = mt + wmr * 32 + (slot >> 1) * 16 + (slot & 1) * 8 + gg;
        g_pmax[(size_t)row * NBLK + blockIdx.y] = M;
        g_psum[(size_t)row * NBLK + blockIdx.y] = S;
    }
}

// ============================================================================
// K4: finalize LSE from per-block partials
// ============================================================================
__global__ void k_lsefin(float* __restrict__ lse) {
    int b = blockIdx.x, t = threadIdx.x;   // 256 threads
    float m = -3.0e38f, s = 0.f;
    for (int i = t; i < NBLK; i += 256) {
        float m2 = g_pmax[(size_t)b * NBLK + i];
        float s2 = g_psum[(size_t)b * NBLK + i];
        float M = fmaxf(m, m2);
        s = s * __expf(m - M) + s2 * __expf(m2 - M);
        m = M;
    }
    __shared__ float sm[256], ss[256];
    sm[t] = m; ss[t] = s;
    __syncthreads();
    for (int o = 128; o > 0; o >>= 1) {
        if (t < o) {
            float m2 = sm[t + o], s2 = ss[t + o];
            float M = fmaxf(sm[t], m2);
            ss[t] = ss[t] * __expf(sm[t] - M) + s2 * __expf(m2 - M);
            sm[t] = M;
        }
        __syncthreads();
    }
    if (t == 0) lse[b] = sm[0] + logf(ss[0]);
}

// ============================================================================
// K5: loss = -mean_b( logits[b, tar[b]-1] - lse[b] )
// ============================================================================
__global__ void k_loss(const float* __restrict__ logits, const float* __restrict__ lse,
                       const int* __restrict__ tar, float* __restrict__ loss_out) {
    __shared__ float red[512];
    int t = threadIdx.x;
    int tg = tar[t] - 1;
    red[t] = logits[(size_t)t * NM1 + tg] - lse[t];
    __syncthreads();
    for (int o = 256; o > 0; o >>= 1) {
        if (t < o) red[t] += red[t + o];
        __syncthreads();
    }
    if (t == 0) loss_out[0] = -red[0] / (float)BB;
}

// ============================================================================
// launch
// ============================================================================
extern "C" void kernel_launch(void* const* d_in, const int* in_sizes, int n_in,
                              void* d_out, int out_size) {
    const float* emb    = (const float*)d_in[0];
    const float* W1     = (const float*)d_in[1];
    const float* W2     = (const float*)d_in[2];
    const float* adjI   = (const float*)d_in[3];
    const float* adjO   = (const float*)d_in[4];
    const float* mask   = (const float*)d_in[5];
    const int*   item   = (const int*)d_in[6];
    const int*   alias_ = (const int*)d_in[7];
    const int*   tar    = (const int*)d_in[8];
    float* out = (float*)d_out;

    float *p_av, *p_h, *p_lse, *p_fb;
    __half *p_lh, *p_eh;
    cudaGetSymbolAddress((void**)&p_av,  g_avlast);
    cudaGetSymbolAddress((void**)&p_h,   g_h);
    cudaGetSymbolAddress((void**)&p_lh,  g_lasth_h);
    cudaGetSymbolAddress((void**)&p_eh,  g_emb_h);
    cudaGetSymbolAddress((void**)&p_lse, g_lse);
    cudaGetSymbolAddress((void**)&p_fb,  g_logits_fb);

    static int smem_set = 0;
    if (!smem_set) {
        cudaFuncSetAttribute(k_logits, cudaFuncAttributeMaxDynamicSharedMemorySize,
                             SMEM_LOGITS_BYTES);
        smem_set = 1;
    }

    const long long NL = (long long)BB * NM1;
    float *loss_ptr, *logits_ptr;
    if ((long long)out_size >= NL + 1)      { loss_ptr = out;  logits_ptr = out + 1; }
    else if ((long long)out_size == NL)     { loss_ptr = p_fb; logits_ptr = out; }
    else                                    { loss_ptr = out;  logits_ptr = p_fb; }

    k_cvt<<<2048, 256>>>(emb, p_eh, NN * DD / 4);                            // emb -> fp16
    k_avlast<<<BB, 256>>>(emb, adjI, adjO, mask, item, alias_);
    k_gemm<<<dim3(D2 / 32, BB / 64), 128>>>(p_av, W1, p_h, BB, D2, D2, 1);   // relu(av@W1)
    k_gemm<<<dim3(DD / 32, BB / 64), 128>>>(p_h, W2, (float*)p_lh, BB, D2, DD, 2); // -> fp16
    k_logits<<<dim3(4, NBLK), 256, SMEM_LOGITS_BYTES>>>(p_lh, p_eh, logits_ptr);
    k_lsefin<<<BB, 256>>>(p_lse);
    k_loss<<<1, 512>>>(logits_ptr, p_lse, tar, loss_ptr);
}

// round 14
// speedup vs baseline: 2.1557x; 1.1408x over previous
#include <cuda_runtime.h>
#include <cuda_fp16.h>
#include <cstdint>

#define BB 512
#define SS 64
#define DD 256
#define NN 100000
#define NM1 99999
#define D2 512
#define NBLK 782            // ceil(99999/128)

// ---- scratch (device globals: no allocation allowed) ----
__device__ __half g_av_h[BB * D2];           // fp16 concat(fs_in,fs_out) rows
__device__ __half g_h_h[BB * D2];            // fp16 relu(av@W1)
__device__ __half g_lasth_h[BB * DD];        // fp16 h@W2
__device__ __half g_W1t[D2 * D2];            // W1^T fp16 [N=512][K=512]
__device__ __half g_W2t[DD * D2];            // W2^T fp16 [N=256][K=512]
__device__ __half g_emb_h[NN * DD];          // fp16 embedding copy (51.2 MB)
__device__ float  g_lse[BB];
__device__ float  g_pmax[BB * NBLK];
__device__ float  g_psum[BB * NBLK];
__device__ float  g_logits_fb[BB * NM1];

// ============================================================================
// K-1a: convert embedding fp32 -> fp16 (grid-stride float4 -> half2 x2)
// ============================================================================
__global__ void k_cvt(const float* __restrict__ src, __half* __restrict__ dst, int n4) {
    int i = blockIdx.x * blockDim.x + threadIdx.x;
    int stride = gridDim.x * blockDim.x;
    const float4* s4 = (const float4*)src;
    __half2* d2 = (__half2*)dst;
    for (; i < n4; i += stride) {
        float4 v = s4[i];
        d2[2 * i]     = __floats2half2_rn(v.x, v.y);
        d2[2 * i + 1] = __floats2half2_rn(v.z, v.w);
    }
}

// ============================================================================
// K-1b: W [K,N] fp32 -> W^T [N,K] fp16 (tiled transpose)
// ============================================================================
__global__ void k_wT(const float* __restrict__ src, __half* __restrict__ dst,
                     int K, int N) {
    __shared__ float tile[32][33];
    int tx = threadIdx.x, ty = threadIdx.y;          // (32, 8)
    int bx = blockIdx.x * 32, by = blockIdx.y * 32;  // n-tile, k-tile
#pragma unroll
    for (int i = 0; i < 32; i += 8)
        tile[ty + i][tx] = src[(size_t)(by + ty + i) * N + bx + tx];
    __syncthreads();
#pragma unroll
    for (int i = 0; i < 32; i += 8)
        dst[(size_t)(bx + ty + i) * K + by + tx] = __float2half_rn(tile[tx][ty + i]);
}

// ============================================================================
// K0: session length -> last id -> gather + dual adjacency row-aggregation
//     output av in fp16 (A operand of the fp16 MLP GEMM)
// ============================================================================
__global__ void k_avlast(const float* __restrict__ emb,
                         const float* __restrict__ adj_in,
                         const float* __restrict__ adj_out,
                         const float* __restrict__ mask,
                         const int* __restrict__ item,
                         const int* __restrict__ alias_) {
    int b = blockIdx.x, t = threadIdx.x;   // 256 threads
    __shared__ float ain[SS], aout[SS];
    __shared__ int items[SS];
    __shared__ int s_last;
    if (t == 0) {
        float s = 0.f;
        for (int i = 0; i < SS; i++) s += mask[b * SS + i];
        int rm = (int)s;
        s_last = alias_[b * SS + rm - 1];
    }
    __syncthreads();
    int last = s_last;
    if (t < SS) {
        ain[t]   = adj_in [((size_t)b * SS + last) * SS + t];
        aout[t]  = adj_out[((size_t)b * SS + last) * SS + t];
        items[t] = item[b * SS + t];
    }
    __syncthreads();
    int d = t;
    float aI = 0.f, aO = 0.f;
#pragma unroll 8
    for (int k = 0; k < SS; k++) {
        float e = emb[(size_t)items[k] * DD + d];
        aI = fmaf(ain[k],  e, aI);
        aO = fmaf(aout[k], e, aO);
    }
    g_av_h[b * D2 + d]      = __float2half_rn(aI);
    g_av_h[b * D2 + DD + d] = __float2half_rn(aO);
}

// ============================================================================
// K1/K2: fp16 tensor-core GEMM  C[M,N] = A[M,K] @ B[N,K]^T
//        128(M)x64(N) tile, 8 warps (4M x 2N), k64 chunks, 2-stage cp.async.
//        relu flag; fp16 output.
// ============================================================================
#define GP 144                          // smem row pitch bytes
#define GA_B (128 * GP)                 // A stage bytes  (18432)
#define GB_B (64 * GP)                  // B stage bytes  (9216)
#define GSTG (GA_B + GB_B)              // 27648
#define SMEM_G16 (2 * GSTG)             // 55296

__device__ __forceinline__ void mma_f16(float* c, uint32_t a0, uint32_t a1,
                                        uint32_t a2, uint32_t a3,
                                        uint32_t b0, uint32_t b1) {
    asm volatile("mma.sync.aligned.m16n8k16.row.col.f32.f16.f16.f32 "
                 "{%0,%1,%2,%3},{%4,%5,%6,%7},{%8,%9},{%0,%1,%2,%3};"
                 : "+f"(c[0]), "+f"(c[1]), "+f"(c[2]), "+f"(c[3])
                 : "r"(a0), "r"(a1), "r"(a2), "r"(a3), "r"(b0), "r"(b1));
}

__global__ __launch_bounds__(256) void k_gemm16(const __half* __restrict__ A,
                                                const __half* __restrict__ B,
                                                __half* __restrict__ C,
                                                int K, int N, int relu, int nchunk) {
    extern __shared__ char gsm[];
    uint32_t sbase = (uint32_t)__cvta_generic_to_shared(gsm);
    int row0 = blockIdx.y * 128, col0 = blockIdx.x * 64;
    int t = threadIdx.x;
    int warp = t >> 5, lane = t & 31;
    int wm = warp >> 1, wn = warp & 1;
    int g = lane >> 2, tq = lane & 3;
    int lr = lane & 7, bq = lane >> 3;
    int rowadd = lr + ((bq & 1) << 3);
    int coladdB = (bq >> 1) << 4;

    uint32_t offA[2], offB[2];
#pragma unroll
    for (int mi = 0; mi < 2; mi++)
        offA[mi] = (uint32_t)((wm * 32 + mi * 16 + rowadd) * GP + coladdB);
#pragma unroll
    for (int np = 0; np < 2; np++)
        offB[np] = (uint32_t)((wn * 32 + np * 16 + rowadd) * GP + coladdB);

    float c[2][4][4];
#pragma unroll
    for (int mi = 0; mi < 2; mi++)
#pragma unroll
        for (int nf = 0; nf < 4; nf++)
#pragma unroll
            for (int q = 0; q < 4; q++) c[mi][nf][q] = 0.f;

    // staging coords
    int rA = t >> 3, cA16 = t & 7;      // +0 / +32 / +64 / +96 rows over u0
    // prologue: stage chunk 0
    {
#pragma unroll
        for (int u0 = 0; u0 < 4; u0++) {
            int r = rA + u0 * 32;
            asm volatile("cp.async.cg.shared.global [%0], [%1], 16;\n"
                :: "r"(sbase + (uint32_t)(r * GP + cA16 * 16)),
                   "l"(A + (size_t)(row0 + r) * K + cA16 * 8));
        }
#pragma unroll
        for (int u0 = 0; u0 < 2; u0++) {
            int r = rA + u0 * 32;
            asm volatile("cp.async.cg.shared.global [%0], [%1], 16;\n"
                :: "r"(sbase + (uint32_t)(GA_B + r * GP + cA16 * 16)),
                   "l"(B + (size_t)(col0 + r) * K + cA16 * 8));
        }
        asm volatile("cp.async.commit_group;");
    }

    for (int s = 0; s < nchunk; s++) {
        if (s + 1 < nchunk) {
            uint32_t dst = sbase + ((s + 1) & 1) * GSTG;
            int k0 = (s + 1) * 64;
#pragma unroll
            for (int u0 = 0; u0 < 4; u0++) {
                int r = rA + u0 * 32;
                asm volatile("cp.async.cg.shared.global [%0], [%1], 16;\n"
                    :: "r"(dst + (uint32_t)(r * GP + cA16 * 16)),
                       "l"(A + (size_t)(row0 + r) * K + k0 + cA16 * 8));
            }
#pragma unroll
            for (int u0 = 0; u0 < 2; u0++) {
                int r = rA + u0 * 32;
                asm volatile("cp.async.cg.shared.global [%0], [%1], 16;\n"
                    :: "r"(dst + (uint32_t)(GA_B + r * GP + cA16 * 16)),
                       "l"(B + (size_t)(col0 + r) * K + k0 + cA16 * 8));
            }
        }
        asm volatile("cp.async.commit_group;");
        asm volatile("cp.async.wait_group 1;");
        __syncthreads();
        uint32_t cAb = sbase + (s & 1) * GSTG;
        uint32_t cBb = cAb + GA_B;
#pragma unroll
        for (int ks = 0; ks < 4; ks++) {
            uint32_t kb = (uint32_t)(ks * 32);
            uint32_t a[2][4];
#pragma unroll
            for (int mi = 0; mi < 2; mi++) {
                asm volatile("ldmatrix.sync.aligned.m8n8.x4.shared.b16 {%0,%1,%2,%3}, [%4];"
                             : "=r"(a[mi][0]), "=r"(a[mi][1]), "=r"(a[mi][2]), "=r"(a[mi][3])
                             : "r"(cAb + offA[mi] + kb));
            }
#pragma unroll
            for (int np = 0; np < 2; np++) {
                uint32_t b0, b1, b2r, b3;
                asm volatile("ldmatrix.sync.aligned.m8n8.x4.shared.b16 {%0,%1,%2,%3}, [%4];"
                             : "=r"(b0), "=r"(b1), "=r"(b2r), "=r"(b3)
                             : "r"(cBb + offB[np] + kb));
#pragma unroll
                for (int mi = 0; mi < 2; mi++) {
                    mma_f16(c[mi][2 * np],     a[mi][0], a[mi][1], a[mi][2], a[mi][3], b0, b2r);
                    mma_f16(c[mi][2 * np + 1], a[mi][0], a[mi][1], a[mi][2], a[mi][3], b1, b3);
                }
            }
        }
        __syncthreads();
    }

#pragma unroll
    for (int mi = 0; mi < 2; mi++) {
        int r0 = row0 + wm * 32 + mi * 16 + g;
#pragma unroll
        for (int nf = 0; nf < 4; nf++) {
            int c0 = col0 + wn * 32 + nf * 8 + 2 * tq;
            float v0 = c[mi][nf][0], v1 = c[mi][nf][1];
            float v2 = c[mi][nf][2], v3 = c[mi][nf][3];
            if (relu) {
                v0 = fmaxf(v0, 0.f); v1 = fmaxf(v1, 0.f);
                v2 = fmaxf(v2, 0.f); v3 = fmaxf(v3, 0.f);
            }
            *(__half2*)&C[(size_t)r0 * N + c0]       = __floats2half2_rn(v0, v1);
            *(__half2*)&C[(size_t)(r0 + 8) * N + c0] = __floats2half2_rn(v2, v3);
        }
    }
}

// ============================================================================
// K3: logits[512,99999] = last_h[512,256] @ emb[1:].T  (FP16 mma m16n8k16)
//     128x128 tile, 8 warps (4M x 2N), K-chunk 64 halves (128B rows),
//     3-buffer mbarrier pipeline, ldmatrix.x4 fragments, fused LSE partials.
// ============================================================================
__device__ __forceinline__ void mbar_wait(uint32_t addr, uint32_t parity) {
    asm volatile(
        "{\n\t.reg .pred P;\n\t"
        "WL%=:\n\t"
        "mbarrier.try_wait.parity.acquire.cta.shared::cta.b64 P, [%0], %1, 0x989680;\n\t"
        "@P bra.uni DN%=;\n\t"
        "bra.uni WL%=;\n\t"
        "DN%=:\n\t}"
        :: "r"(addr), "r"(parity) : "memory");
}

#define PITCHB 144                     // bytes per smem row (conflict-free LDSM)
#define STG_B (128 * PITCHB)           // bytes per stage matrix (18432)
#define NST 3
#define NCHUNK 4                       // 256 K-halves / 64 per chunk
#define SM_CTRL 1024
#define SMEM_LOGITS_BYTES (SM_CTRL + 2 * NST * STG_B)   // 111616 B

__device__ __forceinline__ void stage_logits(uint32_t sA, uint32_t sB,
                                             const __half* __restrict__ Ah,
                                             const __half* __restrict__ embh,
                                             int mt, int nt, int k0, int t) {
#pragma unroll
    for (int u0 = 0; u0 < 4; u0++) {
        int u = t + u0 * 256;
        int r = u >> 3, c16 = u & 7;
        uint32_t da = sA + (uint32_t)(r * PITCHB + c16 * 16);
        const __half* srcA = Ah + (size_t)(mt + r) * DD + k0 + c16 * 8;
        asm volatile("cp.async.cg.shared.global [%0], [%1], 16;\n"
                     :: "r"(da), "l"(srcA));
        int er = nt + 1 + r;
        uint32_t db = sB + (uint32_t)(r * PITCHB + c16 * 16);
        const __half* srcB = embh + (size_t)(er < NN ? er : 0) * DD + k0 + c16 * 8;
        int sz = (er < NN) ? 16 : 0;
        asm volatile("cp.async.cg.shared.global [%0], [%1], 16, %2;\n"
                     :: "r"(db), "l"(srcB), "r"(sz));
    }
}

__global__ __launch_bounds__(256) void k_logits(const __half* __restrict__ Ah,
                                                const __half* __restrict__ embh,
                                                float* __restrict__ out) {
    extern __shared__ float smem[];
    uint32_t sbase = (uint32_t)__cvta_generic_to_shared(smem);
    uint32_t mfull[NST], mempty[NST];
#pragma unroll
    for (int i = 0; i < NST; i++) { mfull[i] = sbase + 16 * i; mempty[i] = sbase + 16 * i + 8; }
    uint32_t sA[NST], sB[NST];
#pragma unroll
    for (int i = 0; i < NST; i++) {
        sA[i] = sbase + SM_CTRL + i * STG_B;
        sB[i] = sbase + SM_CTRL + (NST + i) * STG_B;
    }

    int mt = blockIdx.x * 128;
    int nt = blockIdx.y * 128;
    int t = threadIdx.x;
    int warp = t >> 5, lane = t & 31;
    int wm = warp >> 1, wn = warp & 1;
    int g = lane >> 2, tq = lane & 3;
    int lr = lane & 7, bq = lane >> 3;
    int rowadd = lr + ((bq & 1) << 3);
    int coladdB = (bq >> 1) << 4;

    uint32_t offA[2], offB[4];
#pragma unroll
    for (int mi = 0; mi < 2; mi++)
        offA[mi] = (uint32_t)((wm * 32 + mi * 16 + rowadd) * PITCHB + coladdB);
#pragma unroll
    for (int np = 0; np < 4; np++)
        offB[np] = (uint32_t)((wn * 64 + np * 16 + rowadd) * PITCHB + coladdB);

    float c[2][8][4];
#pragma unroll
    for (int mi = 0; mi < 2; mi++)
#pragma unroll
        for (int ni = 0; ni < 8; ni++)
#pragma unroll
            for (int q = 0; q < 4; q++) c[mi][ni][q] = 0.f;

    if (t == 0) {
#pragma unroll
        for (int i = 0; i < NST; i++) {
            asm volatile("mbarrier.init.shared.b64 [%0], 256;" :: "r"(mfull[i])  : "memory");
            asm volatile("mbarrier.init.shared.b64 [%0], 8;"   :: "r"(mempty[i]) : "memory");
        }
    }
    __syncthreads();

    stage_logits(sA[0], sB[0], Ah, embh, mt, nt, 0, t);
    asm volatile("cp.async.mbarrier.arrive.noinc.shared.b64 [%0];" :: "r"(mfull[0]) : "memory");
    stage_logits(sA[1], sB[1], Ah, embh, mt, nt, 64, t);
    asm volatile("cp.async.mbarrier.arrive.noinc.shared.b64 [%0];" :: "r"(mfull[1]) : "memory");

    for (int s = 0; s < NCHUNK; s++) {
        int u = s + 2;
        if (u < NCHUNK) {
            int b2 = u % NST;
            if (u >= NST)
                mbar_wait(mempty[b2], (uint32_t)(((u - NST) / NST) & 1));
            stage_logits(sA[b2], sB[b2], Ah, embh, mt, nt, u * 64, t);
            asm volatile("cp.async.mbarrier.arrive.noinc.shared.b64 [%0];"
                         :: "r"(mfull[b2]) : "memory");
        }
        int b = s % NST;
        mbar_wait(mfull[b], (uint32_t)((s / NST) & 1));
        uint32_t cA = sA[b], cB = sB[b];
#pragma unroll
        for (int ks = 0; ks < 4; ks++) {
            uint32_t kb = (uint32_t)(ks * 32);
            uint32_t a[2][4];
#pragma unroll
            for (int mi = 0; mi < 2; mi++) {
                asm volatile("ldmatrix.sync.aligned.m8n8.x4.shared.b16 {%0,%1,%2,%3}, [%4];"
                             : "=r"(a[mi][0]), "=r"(a[mi][1]), "=r"(a[mi][2]), "=r"(a[mi][3])
                             : "r"(cA + offA[mi] + kb));
            }
#pragma unroll
            for (int np = 0; np < 4; np++) {
                uint32_t b0, b1, b2r, b3;
                asm volatile("ldmatrix.sync.aligned.m8n8.x4.shared.b16 {%0,%1,%2,%3}, [%4];"
                             : "=r"(b0), "=r"(b1), "=r"(b2r), "=r"(b3)
                             : "r"(cB + offB[np] + kb));
#pragma unroll
                for (int mi = 0; mi < 2; mi++) {
                    mma_f16(c[mi][2 * np],     a[mi][0], a[mi][1], a[mi][2], a[mi][3], b0, b2r);
                    mma_f16(c[mi][2 * np + 1], a[mi][0], a[mi][1], a[mi][2], a[mi][3], b1, b3);
                }
            }
        }
        if (lane == 0)
            asm volatile("mbarrier.arrive.shared.b64 _, [%0];" :: "r"(mempty[b]) : "memory");
    }

    // ---- logits stores ----
#pragma unroll
    for (int mi = 0; mi < 2; mi++) {
        int r0 = mt + wm * 32 + mi * 16 + g;
#pragma unroll
        for (int ni = 0; ni < 8; ni++) {
            int c0 = nt + wn * 64 + ni * 8 + 2 * tq;
            if (c0 < NM1) {
                out[(size_t)r0 * NM1 + c0]       = c[mi][ni][0];
                out[(size_t)(r0 + 8) * NM1 + c0] = c[mi][ni][2];
            }
            if (c0 + 1 < NM1) {
                out[(size_t)r0 * NM1 + c0 + 1]       = c[mi][ni][1];
                out[(size_t)(r0 + 8) * NM1 + c0 + 1] = c[mi][ni][3];
            }
        }
    }

    __syncthreads();

    // ---- fused LSE partials ----
    float* redM = smem + 256;
    float* redS = smem + 512;
#pragma unroll
    for (int slot = 0; slot < 4; slot++) {
        int mi = slot >> 1, h = slot & 1;
        float m = -3.0e38f;
#pragma unroll
        for (int ni = 0; ni < 8; ni++) {
            int cbase = nt + wn * 64 + ni * 8 + 2 * tq;
            float v0 = (cbase     < NM1) ? c[mi][ni][2 * h]     : -3.0e38f;
            float v1 = (cbase + 1 < NM1) ? c[mi][ni][2 * h + 1] : -3.0e38f;
            m = fmaxf(m, fmaxf(v0, v1));
        }
        float sum = 0.f;
#pragma unroll
        for (int ni = 0; ni < 8; ni++) {
            int cbase = nt + wn * 64 + ni * 8 + 2 * tq;
            float v0 = (cbase     < NM1) ? c[mi][ni][2 * h]     : -3.0e38f;
            float v1 = (cbase + 1 < NM1) ? c[mi][ni][2 * h + 1] : -3.0e38f;
            sum += __expf(v0 - m) + __expf(v1 - m);
        }
#pragma unroll
        for (int off = 1; off <= 2; off <<= 1) {
            float m2 = __shfl_xor_sync(0xffffffffu, m, off);
            float s2 = __shfl_xor_sync(0xffffffffu, sum, off);
            float M = fmaxf(m, m2);
            sum = sum * __expf(m - M) + s2 * __expf(m2 - M);
            m = M;
        }
        if (tq == 0) {
            redM[(warp * 4 + slot) * 8 + g] = m;
            redS[(warp * 4 + slot) * 8 + g] = sum;
        }
    }
    __syncthreads();
    if (t < 128) {
        int wmr = t >> 5, slot = (t >> 3) & 3, gg = t & 7;
        int i1 = ((wmr * 2)     * 4 + slot) * 8 + gg;
        int i2 = ((wmr * 2 + 1) * 4 + slot) * 8 + gg;
        float m1 = redM[i1], s1 = redS[i1];
        float m2 = redM[i2], s2 = redS[i2];
        float M = fmaxf(m1, m2);
        float S = s1 * __expf(m1 - M) + s2 * __expf(m2 - M);
        int row = mt + wmr * 32 + (slot >> 1) * 16 + (slot & 1) * 8 + gg;
        g_pmax[(size_t)row * NBLK + blockIdx.y] = M;
        g_psum[(size_t)row * NBLK + blockIdx.y] = S;
    }
}

// ============================================================================
// K4: finalize LSE from per-block partials
// ============================================================================
__global__ void k_lsefin(float* __restrict__ lse) {
    int b = blockIdx.x, t = threadIdx.x;
    float m = -3.0e38f, s = 0.f;
    for (int i = t; i < NBLK; i += 256) {
        float m2 = g_pmax[(size_t)b * NBLK + i];
        float s2 = g_psum[(size_t)b * NBLK + i];
        float M = fmaxf(m, m2);
        s = s * __expf(m - M) + s2 * __expf(m2 - M);
        m = M;
    }
    __shared__ float sm[256], ss[256];
    sm[t] = m; ss[t] = s;
    __syncthreads();
    for (int o = 128; o > 0; o >>= 1) {
        if (t < o) {
            float m2 = sm[t + o], s2 = ss[t + o];
            float M = fmaxf(sm[t], m2);
            ss[t] = ss[t] * __expf(sm[t] - M) + s2 * __expf(m2 - M);
            sm[t] = M;
        }
        __syncthreads();
    }
    if (t == 0) lse[b] = sm[0] + logf(ss[0]);
}

// ============================================================================
// K5: loss = -mean_b( logits[b, tar[b]-1] - lse[b] )
// ============================================================================
__global__ void k_loss(const float* __restrict__ logits, const float* __restrict__ lse,
                       const int* __restrict__ tar, float* __restrict__ loss_out) {
    __shared__ float red[512];
    int t = threadIdx.x;
    int tg = tar[t] - 1;
    red[t] = logits[(size_t)t * NM1 + tg] - lse[t];
    __syncthreads();
    for (int o = 256; o > 0; o >>= 1) {
        if (t < o) red[t] += red[t + o];
        __syncthreads();
    }
    if (t == 0) loss_out[0] = -red[0] / (float)BB;
}

// ============================================================================
// launch
// ============================================================================
extern "C" void kernel_launch(void* const* d_in, const int* in_sizes, int n_in,
                              void* d_out, int out_size) {
    const float* emb    = (const float*)d_in[0];
    const float* W1     = (const float*)d_in[1];
    const float* W2     = (const float*)d_in[2];
    const float* adjI   = (const float*)d_in[3];
    const float* adjO   = (const float*)d_in[4];
    const float* mask   = (const float*)d_in[5];
    const int*   item   = (const int*)d_in[6];
    const int*   alias_ = (const int*)d_in[7];
    const int*   tar    = (const int*)d_in[8];
    float* out = (float*)d_out;

    float *p_lse, *p_fb;
    __half *p_av, *p_hh, *p_lh, *p_eh, *p_w1t, *p_w2t;
    cudaGetSymbolAddress((void**)&p_av,  g_av_h);
    cudaGetSymbolAddress((void**)&p_hh,  g_h_h);
    cudaGetSymbolAddress((void**)&p_lh,  g_lasth_h);
    cudaGetSymbolAddress((void**)&p_eh,  g_emb_h);
    cudaGetSymbolAddress((void**)&p_w1t, g_W1t);
    cudaGetSymbolAddress((void**)&p_w2t, g_W2t);
    cudaGetSymbolAddress((void**)&p_lse, g_lse);
    cudaGetSymbolAddress((void**)&p_fb,  g_logits_fb);

    static int smem_set = 0;
    if (!smem_set) {
        cudaFuncSetAttribute(k_logits, cudaFuncAttributeMaxDynamicSharedMemorySize,
                             SMEM_LOGITS_BYTES);
        cudaFuncSetAttribute(k_gemm16, cudaFuncAttributeMaxDynamicSharedMemorySize,
                             SMEM_G16);
        smem_set = 1;
    }

    const long long NL = (long long)BB * NM1;
    float *loss_ptr, *logits_ptr;
    if ((long long)out_size >= NL + 1)      { loss_ptr = out;  logits_ptr = out + 1; }
    else if ((long long)out_size == NL)     { loss_ptr = p_fb; logits_ptr = out; }
    else                                    { loss_ptr = out;  logits_ptr = p_fb; }

    k_cvt<<<2048, 256>>>(emb, p_eh, NN * DD / 4);                      // emb -> fp16
    k_wT<<<dim3(16, 16), dim3(32, 8)>>>(W1, p_w1t, D2, D2);            // W1^T fp16
    k_wT<<<dim3(8, 16),  dim3(32, 8)>>>(W2, p_w2t, D2, DD);            // W2^T fp16
    k_avlast<<<BB, 256>>>(emb, adjI, adjO, mask, item, alias_);
    k_gemm16<<<dim3(D2 / 64, BB / 128), 256, SMEM_G16>>>(p_av, p_w1t, p_hh,
                                                         D2, D2, 1, 8);  // relu(av@W1)
    k_gemm16<<<dim3(DD / 64, BB / 128), 256, SMEM_G16>>>(p_hh, p_w2t, p_lh,
                                                         D2, DD, 0, 8);  // h@W2
    k_logits<<<dim3(4, NBLK), 256, SMEM_LOGITS_BYTES>>>(p_lh, p_eh, logits_ptr);
    k_lsefin<<<BB, 256>>>(p_lse);
    k_loss<<<1, 512>>>(logits_ptr, p_lse, tar, loss_ptr);
}